// round 10
// baseline (speedup 1.0000x reference)
#include <cuda_runtime.h>
#include <cuda_bf16.h>
#include <cuda_fp16.h>
#include <cstdint>

// ===== Problem constants =====
#define B_    2
#define S_    2048
#define HID_  4096
#define NH_   32
#define NKV_  8
#define HD_   128
#define QSZ   (NH_ * HD_)
#define KVSZ  (NKV_ * HD_)
#define OSZ   (QSZ + 2 * KVSZ)     // 6144
#define TOK   (B_ * S_)            // 4096
#define SCALING 0.08838834764831843f

// ===== Scratch =====
__device__ float g_qkv[TOK * OSZ];
__device__ __half g_hs[TOK * HID_];
__device__ __half g_wq[OSZ * HID_];
__device__ __half g_wo[HID_ * QSZ];
__device__ __half g_at[TOK * QSZ];

// ============================================================================
// PTX helpers
// ============================================================================
__device__ __forceinline__ uint32_t smem_u32(const void* p) {
    uint32_t a;
    asm("{ .reg .u64 t; cvta.to.shared.u64 t, %1; cvt.u32.u64 %0, t; }" : "=r"(a) : "l"(p));
    return a;
}
__device__ __forceinline__ void ldmatrix_x4(uint32_t& r0, uint32_t& r1,
                                            uint32_t& r2, uint32_t& r3, uint32_t addr) {
    asm volatile("ldmatrix.sync.aligned.m8n8.x4.shared.b16 {%0,%1,%2,%3}, [%4];"
                 : "=r"(r0), "=r"(r1), "=r"(r2), "=r"(r3) : "r"(addr));
}
__device__ __forceinline__ void ldmatrix_x4t(uint32_t& r0, uint32_t& r1,
                                             uint32_t& r2, uint32_t& r3, uint32_t addr) {
    asm volatile("ldmatrix.sync.aligned.m8n8.x4.trans.shared.b16 {%0,%1,%2,%3}, [%4];"
                 : "=r"(r0), "=r"(r1), "=r"(r2), "=r"(r3) : "r"(addr));
}
__device__ __forceinline__ void mma_f16(float* d, const uint32_t* a, uint32_t b0, uint32_t b1) {
    asm volatile(
        "mma.sync.aligned.m16n8k16.row.col.f32.f16.f16.f32 "
        "{%0,%1,%2,%3}, {%4,%5,%6,%7}, {%8,%9}, {%0,%1,%2,%3};"
        : "+f"(d[0]), "+f"(d[1]), "+f"(d[2]), "+f"(d[3])
        : "r"(a[0]), "r"(a[1]), "r"(a[2]), "r"(a[3]), "r"(b0), "r"(b1));
}
__device__ __forceinline__ void cp_async16(uint32_t s, const void* g) {
    asm volatile("cp.async.cg.shared.global [%0], [%1], 16;" :: "r"(s), "l"(g) : "memory");
}
#define CP_COMMIT() asm volatile("cp.async.commit_group;" ::: "memory")
#define CP_WAIT1()  asm volatile("cp.async.wait_group 1;" ::: "memory")
#define CP_WAIT0()  asm volatile("cp.async.wait_group 0;" ::: "memory")

__device__ __forceinline__ uint32_t pack_hi_h(float a, float b) {
    __half2 h = __floats2half2_rn(a, b);
    return *(uint32_t*)&h;
}
__device__ __forceinline__ uint32_t pack_lo_h(float a, float b, uint32_t hi) {
    __half2 h = *(__half2*)&hi;
    __half2 l = __floats2half2_rn(a - __half2float(h.x), b - __half2float(h.y));
    return *(uint32_t*)&l;
}

// ============================================================================
// convert kernel: fp32 -> fp16
// ============================================================================
__global__ __launch_bounds__(256) void cvt_h_kernel(const float* __restrict__ in,
                                                    __half* __restrict__ o, int n4) {
    int i = blockIdx.x * blockDim.x + threadIdx.x;
    if (i >= n4) return;
    float4 v = ((const float4*)in)[i];
    ((uint2*)o)[i] = make_uint2(pack_hi_h(v.x, v.y), pack_hi_h(v.z, v.w));
}

// ============================================================================
// fp16 single-pass GEMM: C[M,N] = A[M,K] * B[N,K]^T
// 128x128x64 CTA tile, 128 threads (4 warps, 2m x 2n, warp tile 64x64),
// 3-stage cp.async pipeline, 2 CTAs/SM.
// MMA:LDSM = 4:1 per kk-step (8 ldmatrix.x4 -> 32 HMMA).
// ============================================================================
#define GBK    64
#define GSTR   72                    // fp16 elems per smem row (64 data + 8 pad)
#define GMATB  (128 * GSTR * 2)      // 18432 B
#define GSTAGEB (2 * GMATB)          // 36864 B (A, B)
#define GEMM_SMEM (3 * GSTAGEB)      // 110592 B

__global__ __launch_bounds__(128, 2) void gemm_h1(const __half* __restrict__ A,
                                                  const __half* __restrict__ Bw,
                                                  float* __restrict__ C,
                                                  int N, int K, int nBlkN) {
    extern __shared__ char sm[];
    const uint32_t sb = smem_u32(sm);

    int lin = blockIdx.x;
    int grp = lin / (8 * nBlkN);
    int rem = lin - grp * (8 * nBlkN);
    int bm  = grp * 8 + (rem & 7);
    int bn  = rem >> 3;

    const int t = threadIdx.x, lane = t & 31, wid = t >> 5;
    const int wm = wid & 1, wn = wid >> 1;   // 2m x 2n warps, 64x64 warp tile

    const __half* mats[2] = { A + (size_t)bm * 128 * K, Bw + (size_t)bn * 128 * K };

    float acc[4][8][4];
#pragma unroll
    for (int i = 0; i < 4; i++)
#pragma unroll
        for (int j = 0; j < 8; j++)
#pragma unroll
            for (int k = 0; k < 4; k++) acc[i][j][k] = 0.0f;

    const int nchunk = K / GBK;

    auto issue = [&](int g) {
        const int s = g % 3;
        const uint32_t stg = sb + s * GSTAGEB;
        const int k0 = g * GBK;
#pragma unroll
        for (int m = 0; m < 2; m++) {
            const __half* src = mats[m] + k0;
            const uint32_t dstm = stg + m * GMATB;
#pragma unroll
            for (int i = 0; i < 8; i++) {
                int id  = t + i * 128;         // 0..1023
                int row = id >> 3, c = id & 7;
                cp_async16(dstm + (uint32_t)(row * GSTR + c * 8) * 2,
                           src + (size_t)row * K + c * 8);
            }
        }
        CP_COMMIT();
    };

    auto compute = [&](int st) {
        const uint32_t base = sb + st * GSTAGEB;
        const uint32_t aOff = (uint32_t)((wm * 64 + (lane & 15)) * GSTR + (lane >> 4) * 8) * 2;
        const uint32_t bOff = (uint32_t)((wn * 64 + (lane & 15)) * GSTR + (lane >> 4) * 8) * 2;
#pragma unroll
        for (int kk = 0; kk < 4; kk++) {
            const uint32_t ko = (uint32_t)(kk * 16) * 2;
            uint32_t af[4][4];
#pragma unroll
            for (int mt = 0; mt < 4; mt++) {
                uint32_t off = aOff + (uint32_t)(mt * 16 * GSTR) * 2 + ko;
                ldmatrix_x4(af[mt][0], af[mt][1], af[mt][2], af[mt][3], base + off);
            }
            uint32_t bf[4][4];
#pragma unroll
            for (int g = 0; g < 4; g++) {
                uint32_t off = bOff + (uint32_t)(g * 16 * GSTR) * 2 + ko;
                ldmatrix_x4(bf[g][0], bf[g][1], bf[g][2], bf[g][3], base + GMATB + off);
            }
#pragma unroll
            for (int mt = 0; mt < 4; mt++) {
#pragma unroll
                for (int g = 0; g < 4; g++) {
                    mma_f16(acc[mt][2 * g],     af[mt], bf[g][0], bf[g][2]);
                    mma_f16(acc[mt][2 * g + 1], af[mt], bf[g][1], bf[g][3]);
                }
            }
        }
    };

    issue(0); issue(1);
    for (int c = 0; c < nchunk; c++) {
        if (c < nchunk - 1) { CP_WAIT1(); } else { CP_WAIT0(); }
        __syncthreads();
        if (c + 2 < nchunk) issue(c + 2);   // stage (c-1)%3, consumed in iter c-1
        compute(c % 3);
    }

    const int rowBase = bm * 128 + wm * 64 + (lane >> 2);
    const int colBase = bn * 128 + wn * 64 + (lane & 3) * 2;
#pragma unroll
    for (int mt = 0; mt < 4; mt++) {
#pragma unroll
        for (int nt = 0; nt < 8; nt++) {
            float* c0 = C + (size_t)(rowBase + mt * 16) * N + colBase + nt * 8;
            *(float2*)c0                   = make_float2(acc[mt][nt][0], acc[mt][nt][1]);
            *(float2*)(c0 + (size_t)8 * N) = make_float2(acc[mt][nt][2], acc[mt][nt][3]);
        }
    }
}

// ============================================================================
// RoPE (fp32, in place on g_qkv)
// ============================================================================
__global__ __launch_bounds__(256) void rope_kernel(float* __restrict__ qkv,
                                                   const float* __restrict__ cosb,
                                                   const float* __restrict__ sinb) {
    int p = blockIdx.x * blockDim.x + threadIdx.x;
    int d    = p & 63;
    int rest = p >> 6;
    int hh   = rest % (NH_ + NKV_);
    int bs   = rest / (NH_ + NKV_);
    if (bs >= TOK) return;

    size_t base = (size_t)bs * OSZ;
    int off = (hh < NH_) ? (hh * HD_) : (QSZ + (hh - NH_) * HD_);

    float x1 = qkv[base + off + d];
    float x2 = qkv[base + off + d + 64];
    size_t cb = (size_t)bs * HD_;
    float c1 = cosb[cb + d],      s1 = sinb[cb + d];
    float c2 = cosb[cb + d + 64], s2 = sinb[cb + d + 64];

    qkv[base + off + d]      = x1 * c1 - x2 * s1;
    qkv[base + off + d + 64] = x2 * c2 + x1 * s2;
}

// ============================================================================
// Tensor-core flash attention, fp16 2-pass (unchanged — numerics frozen).
// ============================================================================
#define ASTR 136
#define AQB  (128 * ASTR * 2)
#define AKB  (64 * ASTR * 2)
#define OFF_QH 0
#define OFF_QL (AQB)
#define OFF_K  (2 * AQB)
#define OFF_V  (2 * AQB + AKB)
#define ATTN_SMEM (2 * AQB + 2 * AKB)   // 104448 B

__global__ __launch_bounds__(256, 1) void attn_tc(const float* __restrict__ qkv,
                                                  __half* __restrict__ outh) {
    extern __shared__ char sm[];
    const uint32_t sb = smem_u32(sm);

    const int qt = (int)gridDim.x - 1 - (int)blockIdx.x;
    const int bh = blockIdx.y;
    const int b  = bh >> 5;
    const int h  = bh & 31;
    const int kvh = h >> 2;

    const float* qbase = qkv + (size_t)b * S_ * OSZ + h * HD_;
    const float* kbase = qkv + (size_t)b * S_ * OSZ + QSZ + kvh * HD_;
    const float* vbase = kbase + KVSZ;

    const int t = threadIdx.x, lane = t & 31, wid = t >> 5;
    const int q0 = qt * 128;
    const int wRow = wid * 16;

#pragma unroll
    for (int i = 0; i < 16; i++) {
        int idx = t + i * 256;
        int r   = idx >> 5;
        int c4  = (idx & 31) * 4;
        float4 v = *(const float4*)(qbase + (size_t)(q0 + r) * OSZ + c4);
        v.x *= SCALING; v.y *= SCALING; v.z *= SCALING; v.w *= SCALING;
        uint32_t h01 = pack_hi_h(v.x, v.y), h23 = pack_hi_h(v.z, v.w);
        uint32_t off = (uint32_t)(r * ASTR + c4) * 2;
        *(uint2*)(sm + OFF_QH + off) = make_uint2(h01, h23);
        *(uint2*)(sm + OFF_QL + off) = make_uint2(pack_lo_h(v.x, v.y, h01), pack_lo_h(v.z, v.w, h23));
    }

    float m0 = -1e30f, m1 = -1e30f, l0 = 0.0f, l1 = 0.0f;
    float o[16][4];
#pragma unroll
    for (int i = 0; i < 16; i++)
#pragma unroll
        for (int j = 0; j < 4; j++) o[i][j] = 0.0f;

    const int nkv = qt * 2 + 2;
    for (int kt = 0; kt < nkv; kt++) {
        const int k0 = kt * 64;

        float4 stg[16];
        {
            int r  = t >> 5;
            int c4 = (t & 31) * 4;
#pragma unroll
            for (int i = 0; i < 8; i++)
                stg[i] = *(const float4*)(kbase + (size_t)(k0 + r + i * 8) * OSZ + c4);
#pragma unroll
            for (int i = 0; i < 8; i++)
                stg[8 + i] = *(const float4*)(vbase + (size_t)(k0 + r + i * 8) * OSZ + c4);
        }
        __syncthreads();
        {
            int r  = t >> 5;
            int c4 = (t & 31) * 4;
#pragma unroll
            for (int i = 0; i < 8; i++) {
                uint32_t off = (uint32_t)((r + i * 8) * ASTR + c4) * 2;
                float4 v = stg[i];
                *(uint2*)(sm + OFF_K + off) = make_uint2(pack_hi_h(v.x, v.y), pack_hi_h(v.z, v.w));
                float4 w = stg[8 + i];
                *(uint2*)(sm + OFF_V + off) = make_uint2(pack_hi_h(w.x, w.y), pack_hi_h(w.z, w.w));
            }
        }
        __syncthreads();

        float sacc[8][4];
#pragma unroll
        for (int i = 0; i < 8; i++)
#pragma unroll
            for (int j = 0; j < 4; j++) sacc[i][j] = 0.0f;

        const uint32_t aOff = (uint32_t)((wRow + (lane & 15)) * ASTR + (lane >> 4) * 8) * 2;
        const uint32_t bOff = (uint32_t)(((lane & 15)) * ASTR + (lane >> 4) * 8) * 2;
#pragma unroll
        for (int kk = 0; kk < 8; kk++) {
            const uint32_t ko = (uint32_t)(kk * 16) * 2;
            uint32_t qh[4], ql[4];
            ldmatrix_x4(qh[0], qh[1], qh[2], qh[3], sb + OFF_QH + aOff + ko);
            ldmatrix_x4(ql[0], ql[1], ql[2], ql[3], sb + OFF_QL + aOff + ko);
#pragma unroll
            for (int g = 0; g < 4; g++) {
                uint32_t off = bOff + (uint32_t)(g * 16 * ASTR) * 2 + ko;
                uint32_t kh[4];
                ldmatrix_x4(kh[0], kh[1], kh[2], kh[3], sb + OFF_K + off);
                mma_f16(sacc[2 * g],     qh, kh[0], kh[2]);
                mma_f16(sacc[2 * g],     ql, kh[0], kh[2]);
                mma_f16(sacc[2 * g + 1], qh, kh[1], kh[3]);
                mma_f16(sacc[2 * g + 1], ql, kh[1], kh[3]);
            }
        }

        const int r0 = q0 + wRow + (lane >> 2);
        const int r1 = r0 + 8;
        if (k0 + 63 > q0 + wRow) {
#pragma unroll
            for (int nt = 0; nt < 8; nt++) {
                int c = k0 + nt * 8 + (lane & 3) * 2;
                if (c     > r0) sacc[nt][0] = -1e30f;
                if (c + 1 > r0) sacc[nt][1] = -1e30f;
                if (c     > r1) sacc[nt][2] = -1e30f;
                if (c + 1 > r1) sacc[nt][3] = -1e30f;
            }
        }

        float mx0 = m0, mx1 = m1;
#pragma unroll
        for (int nt = 0; nt < 8; nt++) {
            mx0 = fmaxf(mx0, fmaxf(sacc[nt][0], sacc[nt][1]));
            mx1 = fmaxf(mx1, fmaxf(sacc[nt][2], sacc[nt][3]));
        }
        mx0 = fmaxf(mx0, __shfl_xor_sync(0xFFFFFFFFu, mx0, 1));
        mx0 = fmaxf(mx0, __shfl_xor_sync(0xFFFFFFFFu, mx0, 2));
        mx1 = fmaxf(mx1, __shfl_xor_sync(0xFFFFFFFFu, mx1, 1));
        mx1 = fmaxf(mx1, __shfl_xor_sync(0xFFFFFFFFu, mx1, 2));
        float f0 = __expf(m0 - mx0), f1 = __expf(m1 - mx1);
        float sum0 = 0.0f, sum1 = 0.0f;
#pragma unroll
        for (int nt = 0; nt < 8; nt++) {
            sacc[nt][0] = __expf(sacc[nt][0] - mx0);
            sacc[nt][1] = __expf(sacc[nt][1] - mx0);
            sacc[nt][2] = __expf(sacc[nt][2] - mx1);
            sacc[nt][3] = __expf(sacc[nt][3] - mx1);
            sum0 += sacc[nt][0] + sacc[nt][1];
            sum1 += sacc[nt][2] + sacc[nt][3];
        }
        sum0 += __shfl_xor_sync(0xFFFFFFFFu, sum0, 1);
        sum0 += __shfl_xor_sync(0xFFFFFFFFu, sum0, 2);
        sum1 += __shfl_xor_sync(0xFFFFFFFFu, sum1, 1);
        sum1 += __shfl_xor_sync(0xFFFFFFFFu, sum1, 2);
        m0 = mx0; m1 = mx1;
        l0 = l0 * f0 + sum0;
        l1 = l1 * f1 + sum1;
#pragma unroll
        for (int d = 0; d < 16; d++) {
            o[d][0] *= f0; o[d][1] *= f0; o[d][2] *= f1; o[d][3] *= f1;
        }

#pragma unroll
        for (int kt2 = 0; kt2 < 4; kt2++) {
            uint32_t Ph[4], Pl[4];
            Ph[0] = pack_hi_h(sacc[2 * kt2][0],     sacc[2 * kt2][1]);
            Pl[0] = pack_lo_h(sacc[2 * kt2][0],     sacc[2 * kt2][1],     Ph[0]);
            Ph[1] = pack_hi_h(sacc[2 * kt2][2],     sacc[2 * kt2][3]);
            Pl[1] = pack_lo_h(sacc[2 * kt2][2],     sacc[2 * kt2][3],     Ph[1]);
            Ph[2] = pack_hi_h(sacc[2 * kt2 + 1][0], sacc[2 * kt2 + 1][1]);
            Pl[2] = pack_lo_h(sacc[2 * kt2 + 1][0], sacc[2 * kt2 + 1][1], Ph[2]);
            Ph[3] = pack_hi_h(sacc[2 * kt2 + 1][2], sacc[2 * kt2 + 1][3]);
            Pl[3] = pack_lo_h(sacc[2 * kt2 + 1][2], sacc[2 * kt2 + 1][3], Ph[3]);

            const int kRow = kt2 * 16 + (lane & 7) + ((lane >> 4) & 1) * 8;
#pragma unroll
            for (int gd = 0; gd < 8; gd++) {
                const int nCol = gd * 16 + ((lane >> 3) & 1) * 8;
                const uint32_t off = (uint32_t)(kRow * ASTR + nCol) * 2;
                uint32_t vh[4];
                ldmatrix_x4t(vh[0], vh[1], vh[2], vh[3], sb + OFF_V + off);
                mma_f16(o[2 * gd],     Ph, vh[0], vh[2]);
                mma_f16(o[2 * gd],     Pl, vh[0], vh[2]);
                mma_f16(o[2 * gd + 1], Ph, vh[1], vh[3]);
                mma_f16(o[2 * gd + 1], Pl, vh[1], vh[3]);
            }
        }
    }

    const float i0 = 1.0f / l0, i1 = 1.0f / l1;
    const int tok0 = b * S_ + q0 + wRow + (lane >> 2);
    const int tok1 = tok0 + 8;
    const int colB = h * HD_ + (lane & 3) * 2;
#pragma unroll
    for (int d = 0; d < 16; d++) {
        int col = colB + d * 8;
        *(uint32_t*)(outh + (size_t)tok0 * QSZ + col) = pack_hi_h(o[d][0] * i0, o[d][1] * i0);
        *(uint32_t*)(outh + (size_t)tok1 * QSZ + col) = pack_hi_h(o[d][2] * i1, o[d][3] * i1);
    }
}

// ============================================================================
// kernel_launch
// ============================================================================
extern "C" void kernel_launch(void* const* d_in, const int* in_sizes, int n_in,
                              void* d_out, int out_size) {
    const float* hs    = (const float*)d_in[0];
    const float* cosb  = (const float*)d_in[1];
    const float* sinb  = (const float*)d_in[2];
    const float* w_qkv = (const float*)d_in[3];
    const float* w_o   = (const float*)d_in[4];
    float* out = (float*)d_out;

    float* qkv;  cudaGetSymbolAddress((void**)&qkv, g_qkv);
    __half *hsp, *wq, *wo, *at;
    cudaGetSymbolAddress((void**)&hsp, g_hs);
    cudaGetSymbolAddress((void**)&wq,  g_wq);
    cudaGetSymbolAddress((void**)&wo,  g_wo);
    cudaGetSymbolAddress((void**)&at,  g_at);

    cudaFuncSetAttribute(gemm_h1, cudaFuncAttributeMaxDynamicSharedMemorySize, GEMM_SMEM);
    cudaFuncSetAttribute(attn_tc, cudaFuncAttributeMaxDynamicSharedMemorySize, ATTN_SMEM);

    // 0) operand conversion
    cvt_h_kernel<<<(TOK * HID_ / 4) / 256, 256>>>(hs, hsp, TOK * HID_ / 4);
    cvt_h_kernel<<<(OSZ * HID_ / 4) / 256, 256>>>(w_qkv, wq, OSZ * HID_ / 4);
    cvt_h_kernel<<<(HID_ * QSZ / 4) / 256, 256>>>(w_o, wo, HID_ * QSZ / 4);

    // 1) QKV projection
    gemm_h1<<<(TOK / 128) * (OSZ / 128), 128, GEMM_SMEM>>>(hsp, wq, qkv,
                                                           OSZ, HID_, OSZ / 128);
    // 2) RoPE
    rope_kernel<<<TOK * (NH_ + NKV_) * 64 / 256, 256>>>(qkv, cosb, sinb);

    // 3) Attention
    {
        dim3 grid(S_ / 128, B_ * NH_);
        attn_tc<<<grid, 256, ATTN_SMEM>>>(qkv, at);
    }

    // 4) Output projection
    gemm_h1<<<(TOK / 128) * (HID_ / 128), 128, GEMM_SMEM>>>(at, wo, out,
                                                            HID_, QSZ, HID_ / 128);
}

// round 11
// speedup vs baseline: 1.0787x; 1.0787x over previous
#include <cuda_runtime.h>
#include <cuda_bf16.h>
#include <cuda_fp16.h>
#include <cstdint>

// ===== Problem constants =====
#define B_    2
#define S_    2048
#define HID_  4096
#define NH_   32
#define NKV_  8
#define HD_   128
#define QSZ   (NH_ * HD_)
#define KVSZ  (NKV_ * HD_)
#define OSZ   (QSZ + 2 * KVSZ)     // 6144
#define TOK   (B_ * S_)            // 4096
#define SCALING 0.08838834764831843f

// ===== Scratch =====
__device__ __half g_hs[TOK * HID_];
__device__ __half g_wq[OSZ * HID_];
__device__ __half g_wo[HID_ * QSZ];
__device__ __half g_qh[TOK * QSZ], g_ql[TOK * QSZ];   // roped+scaled Q hi/lo
__device__ __half g_k [TOK * KVSZ];                    // roped K fp16
__device__ __half g_v [TOK * KVSZ];                    // V fp16
__device__ __half g_at[TOK * QSZ];                     // attention out fp16

// ============================================================================
// PTX helpers
// ============================================================================
__device__ __forceinline__ uint32_t smem_u32(const void* p) {
    uint32_t a;
    asm("{ .reg .u64 t; cvta.to.shared.u64 t, %1; cvt.u32.u64 %0, t; }" : "=r"(a) : "l"(p));
    return a;
}
__device__ __forceinline__ void ldmatrix_x4(uint32_t& r0, uint32_t& r1,
                                            uint32_t& r2, uint32_t& r3, uint32_t addr) {
    asm volatile("ldmatrix.sync.aligned.m8n8.x4.shared.b16 {%0,%1,%2,%3}, [%4];"
                 : "=r"(r0), "=r"(r1), "=r"(r2), "=r"(r3) : "r"(addr));
}
__device__ __forceinline__ void ldmatrix_x4t(uint32_t& r0, uint32_t& r1,
                                             uint32_t& r2, uint32_t& r3, uint32_t addr) {
    asm volatile("ldmatrix.sync.aligned.m8n8.x4.trans.shared.b16 {%0,%1,%2,%3}, [%4];"
                 : "=r"(r0), "=r"(r1), "=r"(r2), "=r"(r3) : "r"(addr));
}
__device__ __forceinline__ void mma_f16(float* d, const uint32_t* a, uint32_t b0, uint32_t b1) {
    asm volatile(
        "mma.sync.aligned.m16n8k16.row.col.f32.f16.f16.f32 "
        "{%0,%1,%2,%3}, {%4,%5,%6,%7}, {%8,%9}, {%0,%1,%2,%3};"
        : "+f"(d[0]), "+f"(d[1]), "+f"(d[2]), "+f"(d[3])
        : "r"(a[0]), "r"(a[1]), "r"(a[2]), "r"(a[3]), "r"(b0), "r"(b1));
}
__device__ __forceinline__ void cp_async16(uint32_t s, const void* g) {
    asm volatile("cp.async.cg.shared.global [%0], [%1], 16;" :: "r"(s), "l"(g) : "memory");
}
#define CP_COMMIT() asm volatile("cp.async.commit_group;" ::: "memory")
#define CP_WAIT1()  asm volatile("cp.async.wait_group 1;" ::: "memory")
#define CP_WAIT0()  asm volatile("cp.async.wait_group 0;" ::: "memory")

__device__ __forceinline__ uint32_t pack_hi_h(float a, float b) {
    __half2 h = __floats2half2_rn(a, b);
    return *(uint32_t*)&h;
}
__device__ __forceinline__ uint32_t pack_lo_h(float a, float b, uint32_t hi) {
    __half2 h = *(__half2*)&hi;
    __half2 l = __floats2half2_rn(a - __half2float(h.x), b - __half2float(h.y));
    return *(uint32_t*)&l;
}

// ============================================================================
// convert kernel: fp32 -> fp16
// ============================================================================
__global__ __launch_bounds__(256) void cvt_h_kernel(const float* __restrict__ in,
                                                    __half* __restrict__ o, int n4) {
    int i = blockIdx.x * blockDim.x + threadIdx.x;
    if (i >= n4) return;
    float4 v = ((const float4*)in)[i];
    ((uint2*)o)[i] = make_uint2(pack_hi_h(v.x, v.y), pack_hi_h(v.z, v.w));
}

// ============================================================================
// Shared GEMM config (R9-validated: 512 threads, 16 warps 4m x 4n, 32x32
// warp tile, 3-stage cp.async, 2 CTAs/SM)
// ============================================================================
#define GBK    64
#define GSTR   72
#define GMATB  (128 * GSTR * 2)      // 18432 B
#define GSTAGEB (2 * GMATB)          // 36864 B
#define GEMM_SMEM (3 * GSTAGEB)      // 110592 B

// main-loop body shared by both GEMM kernels (macro to keep lambdas local)
#define GEMM_MAINLOOP(A_, B_ptr, Kdim)                                            \
    const __half* mats[2] = { A_, B_ptr };                                        \
    float acc[2][4][4];                                                           \
    _Pragma("unroll") for (int i = 0; i < 2; i++)                                 \
        _Pragma("unroll") for (int j = 0; j < 4; j++)                             \
            _Pragma("unroll") for (int k = 0; k < 4; k++) acc[i][j][k] = 0.0f;    \
    const int nchunk = (Kdim) / GBK;                                              \
    auto issue = [&](int g) {                                                     \
        const int s = g % 3;                                                      \
        const uint32_t stg = sb + s * GSTAGEB;                                    \
        const int k0 = g * GBK;                                                   \
        _Pragma("unroll") for (int m = 0; m < 2; m++) {                           \
            const __half* src = mats[m] + k0;                                     \
            const uint32_t dstm = stg + m * GMATB;                                \
            _Pragma("unroll") for (int i = 0; i < 2; i++) {                       \
                int id  = t + i * 512;                                            \
                int row = id >> 3, c = id & 7;                                    \
                cp_async16(dstm + (uint32_t)(row * GSTR + c * 8) * 2,             \
                           src + (size_t)row * (Kdim) + c * 8);                   \
            }                                                                     \
        }                                                                         \
        CP_COMMIT();                                                              \
    };                                                                            \
    auto compute = [&](int st) {                                                  \
        const uint32_t base = sb + st * GSTAGEB;                                  \
        const uint32_t aOff = (uint32_t)((wm * 32 + (lane & 15)) * GSTR + (lane >> 4) * 8) * 2; \
        const uint32_t bOff = (uint32_t)((wn * 32 + (lane & 15)) * GSTR + (lane >> 4) * 8) * 2; \
        _Pragma("unroll") for (int kk = 0; kk < 4; kk++) {                        \
            const uint32_t ko = (uint32_t)(kk * 16) * 2;                          \
            uint32_t af[2][4];                                                    \
            _Pragma("unroll") for (int mt = 0; mt < 2; mt++) {                    \
                uint32_t off = aOff + (uint32_t)(mt * 16 * GSTR) * 2 + ko;        \
                ldmatrix_x4(af[mt][0], af[mt][1], af[mt][2], af[mt][3], base + off); \
            }                                                                     \
            uint32_t bf[2][4];                                                    \
            _Pragma("unroll") for (int g = 0; g < 2; g++) {                       \
                uint32_t off = bOff + (uint32_t)(g * 16 * GSTR) * 2 + ko;         \
                ldmatrix_x4(bf[g][0], bf[g][1], bf[g][2], bf[g][3], base + GMATB + off); \
            }                                                                     \
            _Pragma("unroll") for (int mt = 0; mt < 2; mt++) {                    \
                _Pragma("unroll") for (int g = 0; g < 2; g++) {                   \
                    mma_f16(acc[mt][2 * g],     af[mt], bf[g][0], bf[g][2]);      \
                    mma_f16(acc[mt][2 * g + 1], af[mt], bf[g][1], bf[g][3]);      \
                }                                                                 \
            }                                                                     \
        }                                                                         \
    };                                                                            \
    issue(0); issue(1);                                                           \
    for (int c = 0; c < nchunk; c++) {                                            \
        if (c < nchunk - 1) { CP_WAIT1(); } else { CP_WAIT0(); }                  \
        __syncthreads();                                                          \
        if (c + 2 < nchunk) issue(c + 2);                                         \
        compute(c % 3);                                                           \
    }

// ============================================================================
// GEMM2: C[M,N] = A * B^T, fp32 out (final output projection)
// ============================================================================
__global__ __launch_bounds__(512, 2) void gemm_h1(const __half* __restrict__ A,
                                                  const __half* __restrict__ Bw,
                                                  float* __restrict__ C,
                                                  int N, int K, int nBlkN) {
    extern __shared__ char sm[];
    const uint32_t sb = smem_u32(sm);

    int lin = blockIdx.x;
    int grp = lin / (8 * nBlkN);
    int rem = lin - grp * (8 * nBlkN);
    int bm  = grp * 8 + (rem & 7);
    int bn  = rem >> 3;

    const int t = threadIdx.x, lane = t & 31, wid = t >> 5;
    const int wm = wid & 3, wn = wid >> 2;

    GEMM_MAINLOOP(A + (size_t)bm * 128 * K, Bw + (size_t)bn * 128 * K, K)

    const int rowBase = bm * 128 + wm * 32 + (lane >> 2);
    const int colBase = bn * 128 + wn * 32 + (lane & 3) * 2;
#pragma unroll
    for (int mt = 0; mt < 2; mt++) {
#pragma unroll
        for (int nt = 0; nt < 4; nt++) {
            float* c0 = C + (size_t)(rowBase + mt * 16) * N + colBase + nt * 8;
            *(float2*)c0                   = make_float2(acc[mt][nt][0], acc[mt][nt][1]);
            *(float2*)(c0 + (size_t)8 * N) = make_float2(acc[mt][nt][2], acc[mt][nt][3]);
        }
    }
}

// ============================================================================
// GEMM1 + fused RoPE + fp16 split epilogue.
// bn<32 -> Q head bn (rope, scale, hi/lo); 32..39 -> K head bn-32 (rope, fp16);
// 40..47 -> V head bn-40 (fp16).
// ============================================================================
#define TSTR 132   // fp32 tile row stride in epilogue

__global__ __launch_bounds__(512, 2) void gemm_qkv(const __half* __restrict__ A,
                                                   const __half* __restrict__ Bw,
                                                   const float* __restrict__ cosb,
                                                   const float* __restrict__ sinb,
                                                   __half* __restrict__ qh,
                                                   __half* __restrict__ ql,
                                                   __half* __restrict__ kOut,
                                                   __half* __restrict__ vOut) {
    extern __shared__ char sm[];
    const uint32_t sb = smem_u32(sm);
    const int nBlkN = OSZ / 128;

    int lin = blockIdx.x;
    int grp = lin / (8 * nBlkN);
    int rem = lin - grp * (8 * nBlkN);
    int bm  = grp * 8 + (rem & 7);
    int bn  = rem >> 3;

    const int t = threadIdx.x, lane = t & 31, wid = t >> 5;
    const int wm = wid & 3, wn = wid >> 2;

    GEMM_MAINLOOP(A + (size_t)bm * 128 * HID_, Bw + (size_t)bn * 128 * HID_, HID_)

    // ---- epilogue: acc -> smem fp32 tile -> rope/split -> fp16 ----
    __syncthreads();                       // all warps done with pipeline smem
    float* tile = (float*)sm;              // 128 x 132 fp32 = 67584 B <= 110592
    {
        const int r0 = wm * 32 + (lane >> 2);
        const int c0 = wn * 32 + (lane & 3) * 2;
#pragma unroll
        for (int mt = 0; mt < 2; mt++) {
#pragma unroll
            for (int nt = 0; nt < 4; nt++) {
                int r = r0 + mt * 16, c = c0 + nt * 8;
                *(float2*)&tile[r * TSTR + c]       = make_float2(acc[mt][nt][0], acc[mt][nt][1]);
                *(float2*)&tile[(r + 8) * TSTR + c] = make_float2(acc[mt][nt][2], acc[mt][nt][3]);
            }
        }
    }
    __syncthreads();

    // 512 threads: row r = t>>2, quarter q = t&3
    const int r  = t >> 2;
    const int qq = t & 3;
    const int tok = bm * 128 + r;
    const float* tr = tile + r * TSTR;

    if (bn < 40) {
        // rope: quarter handles pair-cols d = qq*16 .. qq*16+15
        const float4* cp = (const float4*)(cosb + (size_t)tok * HD_);
        const float4* sp = (const float4*)(sinb + (size_t)tok * HD_);
        const bool isQ = bn < 32;
        size_t base = isQ ? ((size_t)tok * QSZ + bn * 128)
                          : ((size_t)tok * KVSZ + (bn - 32) * 128);
#pragma unroll
        for (int i = 0; i < 4; i++) {
            int d = qq * 16 + i * 4;
            float4 x1 = *(const float4*)&tr[d];
            float4 x2 = *(const float4*)&tr[d + 64];
            float4 c1 = cp[d >> 2],        s1 = sp[d >> 2];
            float4 c2 = cp[(d + 64) >> 2], s2 = sp[(d + 64) >> 2];
            float4 y1 = make_float4(x1.x * c1.x - x2.x * s1.x, x1.y * c1.y - x2.y * s1.y,
                                    x1.z * c1.z - x2.z * s1.z, x1.w * c1.w - x2.w * s1.w);
            float4 y2 = make_float4(x2.x * c2.x + x1.x * s2.x, x2.y * c2.y + x1.y * s2.y,
                                    x2.z * c2.z + x1.z * s2.z, x2.w * c2.w + x1.w * s2.w);
            if (isQ) {
                y1.x *= SCALING; y1.y *= SCALING; y1.z *= SCALING; y1.w *= SCALING;
                y2.x *= SCALING; y2.y *= SCALING; y2.z *= SCALING; y2.w *= SCALING;
                uint32_t a01 = pack_hi_h(y1.x, y1.y), a23 = pack_hi_h(y1.z, y1.w);
                uint32_t b01 = pack_hi_h(y2.x, y2.y), b23 = pack_hi_h(y2.z, y2.w);
                *(uint2*)(qh + base + d)      = make_uint2(a01, a23);
                *(uint2*)(qh + base + d + 64) = make_uint2(b01, b23);
                *(uint2*)(ql + base + d)      = make_uint2(pack_lo_h(y1.x, y1.y, a01),
                                                           pack_lo_h(y1.z, y1.w, a23));
                *(uint2*)(ql + base + d + 64) = make_uint2(pack_lo_h(y2.x, y2.y, b01),
                                                           pack_lo_h(y2.z, y2.w, b23));
            } else {
                *(uint2*)(kOut + base + d)      = make_uint2(pack_hi_h(y1.x, y1.y), pack_hi_h(y1.z, y1.w));
                *(uint2*)(kOut + base + d + 64) = make_uint2(pack_hi_h(y2.x, y2.y), pack_hi_h(y2.z, y2.w));
            }
        }
    } else {
        // V: quarter handles d = qq*32 .. qq*32+31
        size_t base = (size_t)tok * KVSZ + (bn - 40) * 128;
#pragma unroll
        for (int i = 0; i < 8; i++) {
            int d = qq * 32 + i * 4;
            float4 x = *(const float4*)&tr[d];
            *(uint2*)(vOut + base + d) = make_uint2(pack_hi_h(x.x, x.y), pack_hi_h(x.z, x.w));
        }
    }
}

// ============================================================================
// Tensor-core flash attention: fp16 inputs (pre-roped), cp.async K/V double
// buffer, QK 2-pass (Q hi/lo), PV single-pass.
// ============================================================================
#define ASTR 136
#define AQB  (128 * ASTR * 2)        // 34816 B
#define AKB  (64 * ASTR * 2)         // 17408 B
#define OFF_QH 0
#define OFF_QL AQB
#define OFF_KV(s) (2 * AQB + (s) * 2 * AKB)   // K at +0, V at +AKB
#define ATTN_SMEM (2 * AQB + 4 * AKB)         // 139264 B

__global__ __launch_bounds__(256, 1) void attn_tc(const __half* __restrict__ qhp,
                                                  const __half* __restrict__ qlp,
                                                  const __half* __restrict__ kp,
                                                  const __half* __restrict__ vp,
                                                  __half* __restrict__ outh) {
    extern __shared__ char sm[];
    const uint32_t sb = smem_u32(sm);

    const int qt = (int)gridDim.x - 1 - (int)blockIdx.x;
    const int bh = blockIdx.y;
    const int b  = bh >> 5;
    const int h  = bh & 31;
    const int kvh = h >> 2;

    const __half* kbase = kp + (size_t)b * S_ * KVSZ + kvh * HD_;
    const __half* vbase = vp + (size_t)b * S_ * KVSZ + kvh * HD_;

    const int t = threadIdx.x, lane = t & 31, wid = t >> 5;
    const int q0 = qt * 128;
    const int wRow = wid * 16;

    // ---- load Q hi/lo tiles (fp16 copy) ----
#pragma unroll
    for (int i = 0; i < 8; i++) {
        int idx = t + i * 256;              // 0..2047 = 128 rows x 16 units
        int r   = idx >> 4;
        int u   = idx & 15;
        size_t src = (size_t)(b * S_ + q0 + r) * QSZ + h * HD_ + u * 8;
        uint32_t off = (uint32_t)(r * ASTR + u * 8) * 2;
        *(uint4*)(sm + OFF_QH + off) = *(const uint4*)(qhp + src);
        *(uint4*)(sm + OFF_QL + off) = *(const uint4*)(qlp + src);
    }

    const int nkv = qt * 2 + 2;

    auto issue_kv = [&](int kt) {
        const int s = kt & 1;
        const int k0 = kt * 64;
#pragma unroll
        for (int i = 0; i < 4; i++) {
            int idx = t + i * 256;          // 0..1023 = 64 rows x 16 units
            int r   = idx >> 4;
            int u   = idx & 15;
            uint32_t off = (uint32_t)(r * ASTR + u * 8) * 2;
            cp_async16(sb + OFF_KV(s) + off,       kbase + (size_t)(k0 + r) * KVSZ + u * 8);
            cp_async16(sb + OFF_KV(s) + AKB + off, vbase + (size_t)(k0 + r) * KVSZ + u * 8);
        }
        CP_COMMIT();
    };

    float m0 = -1e30f, m1 = -1e30f, l0 = 0.0f, l1 = 0.0f;
    float o[16][4];
#pragma unroll
    for (int i = 0; i < 16; i++)
#pragma unroll
        for (int j = 0; j < 4; j++) o[i][j] = 0.0f;

    issue_kv(0);
    for (int kt = 0; kt < nkv; kt++) {
        const int k0 = kt * 64;
        const int st = kt & 1;
        CP_WAIT0();
        __syncthreads();                    // KV(st) ready; prev reads of KV(st^1) done
        if (kt + 1 < nkv) issue_kv(kt + 1);

        // ---- S = Q K^T (2-pass hi/lo) ----
        float sacc[8][4];
#pragma unroll
        for (int i = 0; i < 8; i++)
#pragma unroll
            for (int j = 0; j < 4; j++) sacc[i][j] = 0.0f;

        const uint32_t aOff = (uint32_t)((wRow + (lane & 15)) * ASTR + (lane >> 4) * 8) * 2;
        const uint32_t bOff = (uint32_t)(((lane & 15)) * ASTR + (lane >> 4) * 8) * 2;
        const uint32_t kvK = sb + OFF_KV(st);
        const uint32_t kvV = kvK + AKB;
#pragma unroll
        for (int kk = 0; kk < 8; kk++) {
            const uint32_t ko = (uint32_t)(kk * 16) * 2;
            uint32_t qhf[4], qlf[4];
            ldmatrix_x4(qhf[0], qhf[1], qhf[2], qhf[3], sb + OFF_QH + aOff + ko);
            ldmatrix_x4(qlf[0], qlf[1], qlf[2], qlf[3], sb + OFF_QL + aOff + ko);
#pragma unroll
            for (int g = 0; g < 4; g++) {
                uint32_t off = bOff + (uint32_t)(g * 16 * ASTR) * 2 + ko;
                uint32_t kh[4];
                ldmatrix_x4(kh[0], kh[1], kh[2], kh[3], kvK + off);
                mma_f16(sacc[2 * g],     qhf, kh[0], kh[2]);
                mma_f16(sacc[2 * g],     qlf, kh[0], kh[2]);
                mma_f16(sacc[2 * g + 1], qhf, kh[1], kh[3]);
                mma_f16(sacc[2 * g + 1], qlf, kh[1], kh[3]);
            }
        }

        // ---- causal mask ----
        const int r0 = q0 + wRow + (lane >> 2);
        const int r1 = r0 + 8;
        if (k0 + 63 > q0 + wRow) {
#pragma unroll
            for (int nt = 0; nt < 8; nt++) {
                int c = k0 + nt * 8 + (lane & 3) * 2;
                if (c     > r0) sacc[nt][0] = -1e30f;
                if (c + 1 > r0) sacc[nt][1] = -1e30f;
                if (c     > r1) sacc[nt][2] = -1e30f;
                if (c + 1 > r1) sacc[nt][3] = -1e30f;
            }
        }

        // ---- online softmax ----
        float mx0 = m0, mx1 = m1;
#pragma unroll
        for (int nt = 0; nt < 8; nt++) {
            mx0 = fmaxf(mx0, fmaxf(sacc[nt][0], sacc[nt][1]));
            mx1 = fmaxf(mx1, fmaxf(sacc[nt][2], sacc[nt][3]));
        }
        mx0 = fmaxf(mx0, __shfl_xor_sync(0xFFFFFFFFu, mx0, 1));
        mx0 = fmaxf(mx0, __shfl_xor_sync(0xFFFFFFFFu, mx0, 2));
        mx1 = fmaxf(mx1, __shfl_xor_sync(0xFFFFFFFFu, mx1, 1));
        mx1 = fmaxf(mx1, __shfl_xor_sync(0xFFFFFFFFu, mx1, 2));
        float f0 = __expf(m0 - mx0), f1 = __expf(m1 - mx1);
        float sum0 = 0.0f, sum1 = 0.0f;
#pragma unroll
        for (int nt = 0; nt < 8; nt++) {
            sacc[nt][0] = __expf(sacc[nt][0] - mx0);
            sacc[nt][1] = __expf(sacc[nt][1] - mx0);
            sacc[nt][2] = __expf(sacc[nt][2] - mx1);
            sacc[nt][3] = __expf(sacc[nt][3] - mx1);
            sum0 += sacc[nt][0] + sacc[nt][1];
            sum1 += sacc[nt][2] + sacc[nt][3];
        }
        sum0 += __shfl_xor_sync(0xFFFFFFFFu, sum0, 1);
        sum0 += __shfl_xor_sync(0xFFFFFFFFu, sum0, 2);
        sum1 += __shfl_xor_sync(0xFFFFFFFFu, sum1, 1);
        sum1 += __shfl_xor_sync(0xFFFFFFFFu, sum1, 2);
        m0 = mx0; m1 = mx1;
        l0 = l0 * f0 + sum0;
        l1 = l1 * f1 + sum1;
#pragma unroll
        for (int d = 0; d < 16; d++) {
            o[d][0] *= f0; o[d][1] *= f0; o[d][2] *= f1; o[d][3] *= f1;
        }

        // ---- O += P V (single-pass fp16 P) ----
#pragma unroll
        for (int kt2 = 0; kt2 < 4; kt2++) {
            uint32_t Ph[4];
            Ph[0] = pack_hi_h(sacc[2 * kt2][0],     sacc[2 * kt2][1]);
            Ph[1] = pack_hi_h(sacc[2 * kt2][2],     sacc[2 * kt2][3]);
            Ph[2] = pack_hi_h(sacc[2 * kt2 + 1][0], sacc[2 * kt2 + 1][1]);
            Ph[3] = pack_hi_h(sacc[2 * kt2 + 1][2], sacc[2 * kt2 + 1][3]);

            const int kRow = kt2 * 16 + (lane & 7) + ((lane >> 4) & 1) * 8;
#pragma unroll
            for (int gd = 0; gd < 8; gd++) {
                const int nCol = gd * 16 + ((lane >> 3) & 1) * 8;
                const uint32_t off = (uint32_t)(kRow * ASTR + nCol) * 2;
                uint32_t vh[4];
                ldmatrix_x4t(vh[0], vh[1], vh[2], vh[3], kvV + off);
                mma_f16(o[2 * gd],     Ph, vh[0], vh[2]);
                mma_f16(o[2 * gd + 1], Ph, vh[1], vh[3]);
            }
        }
    }

    // ---- epilogue ----
    const float i0 = 1.0f / l0, i1 = 1.0f / l1;
    const int tok0 = b * S_ + q0 + wRow + (lane >> 2);
    const int tok1 = tok0 + 8;
    const int colB = h * HD_ + (lane & 3) * 2;
#pragma unroll
    for (int d = 0; d < 16; d++) {
        int col = colB + d * 8;
        *(uint32_t*)(outh + (size_t)tok0 * QSZ + col) = pack_hi_h(o[d][0] * i0, o[d][1] * i0);
        *(uint32_t*)(outh + (size_t)tok1 * QSZ + col) = pack_hi_h(o[d][2] * i1, o[d][3] * i1);
    }
}

// ============================================================================
// kernel_launch
// ============================================================================
extern "C" void kernel_launch(void* const* d_in, const int* in_sizes, int n_in,
                              void* d_out, int out_size) {
    const float* hs    = (const float*)d_in[0];
    const float* cosb  = (const float*)d_in[1];
    const float* sinb  = (const float*)d_in[2];
    const float* w_qkv = (const float*)d_in[3];
    const float* w_o   = (const float*)d_in[4];
    float* out = (float*)d_out;

    __half *hsp, *wq, *wo, *qh, *ql, *kk, *vv, *at;
    cudaGetSymbolAddress((void**)&hsp, g_hs);
    cudaGetSymbolAddress((void**)&wq,  g_wq);
    cudaGetSymbolAddress((void**)&wo,  g_wo);
    cudaGetSymbolAddress((void**)&qh,  g_qh);
    cudaGetSymbolAddress((void**)&ql,  g_ql);
    cudaGetSymbolAddress((void**)&kk,  g_k);
    cudaGetSymbolAddress((void**)&vv,  g_v);
    cudaGetSymbolAddress((void**)&at,  g_at);

    cudaFuncSetAttribute(gemm_qkv, cudaFuncAttributeMaxDynamicSharedMemorySize, GEMM_SMEM);
    cudaFuncSetAttribute(gemm_h1,  cudaFuncAttributeMaxDynamicSharedMemorySize, GEMM_SMEM);
    cudaFuncSetAttribute(attn_tc,  cudaFuncAttributeMaxDynamicSharedMemorySize, ATTN_SMEM);

    // 0) operand conversion
    cvt_h_kernel<<<(TOK * HID_ / 4) / 256, 256>>>(hs, hsp, TOK * HID_ / 4);
    cvt_h_kernel<<<(OSZ * HID_ / 4) / 256, 256>>>(w_qkv, wq, OSZ * HID_ / 4);
    cvt_h_kernel<<<(HID_ * QSZ / 4) / 256, 256>>>(w_o, wo, HID_ * QSZ / 4);

    // 1) QKV projection + fused RoPE + fp16 split
    gemm_qkv<<<(TOK / 128) * (OSZ / 128), 512, GEMM_SMEM>>>(hsp, wq, cosb, sinb,
                                                            qh, ql, kk, vv);

    // 2) Attention
    {
        dim3 grid(S_ / 128, B_ * NH_);
        attn_tc<<<grid, 256, ATTN_SMEM>>>(qh, ql, kk, vv, at);
    }

    // 3) Output projection
    gemm_h1<<<(TOK / 128) * (HID_ / 128), 512, GEMM_SMEM>>>(at, wo, out,
                                                            HID_, QSZ, HID_ / 128);
}

// round 12
// speedup vs baseline: 1.1435x; 1.0601x over previous
#include <cuda_runtime.h>
#include <cuda_bf16.h>
#include <cuda_fp16.h>
#include <cstdint>

// ===== Problem constants =====
#define B_    2
#define S_    2048
#define HID_  4096
#define NH_   32
#define NKV_  8
#define HD_   128
#define QSZ   (NH_ * HD_)
#define KVSZ  (NKV_ * HD_)
#define OSZ   (QSZ + 2 * KVSZ)     // 6144
#define TOK   (B_ * S_)            // 4096
#define SCALING 0.08838834764831843f

// ===== Scratch =====
__device__ __half g_hs[TOK * HID_];
__device__ __half g_wq[OSZ * HID_];
__device__ __half g_wo[HID_ * QSZ];
__device__ __half g_q [TOK * QSZ];                     // roped+scaled Q fp16
__device__ __half g_k [TOK * KVSZ];                    // roped K fp16
__device__ __half g_v [TOK * KVSZ];                    // V fp16
__device__ __half g_at[TOK * QSZ];                     // attention out fp16

// ============================================================================
// PTX helpers
// ============================================================================
__device__ __forceinline__ uint32_t smem_u32(const void* p) {
    uint32_t a;
    asm("{ .reg .u64 t; cvta.to.shared.u64 t, %1; cvt.u32.u64 %0, t; }" : "=r"(a) : "l"(p));
    return a;
}
__device__ __forceinline__ void ldmatrix_x4(uint32_t& r0, uint32_t& r1,
                                            uint32_t& r2, uint32_t& r3, uint32_t addr) {
    asm volatile("ldmatrix.sync.aligned.m8n8.x4.shared.b16 {%0,%1,%2,%3}, [%4];"
                 : "=r"(r0), "=r"(r1), "=r"(r2), "=r"(r3) : "r"(addr));
}
__device__ __forceinline__ void ldmatrix_x4t(uint32_t& r0, uint32_t& r1,
                                             uint32_t& r2, uint32_t& r3, uint32_t addr) {
    asm volatile("ldmatrix.sync.aligned.m8n8.x4.trans.shared.b16 {%0,%1,%2,%3}, [%4];"
                 : "=r"(r0), "=r"(r1), "=r"(r2), "=r"(r3) : "r"(addr));
}
__device__ __forceinline__ void mma_f16(float* d, const uint32_t* a, uint32_t b0, uint32_t b1) {
    asm volatile(
        "mma.sync.aligned.m16n8k16.row.col.f32.f16.f16.f32 "
        "{%0,%1,%2,%3}, {%4,%5,%6,%7}, {%8,%9}, {%0,%1,%2,%3};"
        : "+f"(d[0]), "+f"(d[1]), "+f"(d[2]), "+f"(d[3])
        : "r"(a[0]), "r"(a[1]), "r"(a[2]), "r"(a[3]), "r"(b0), "r"(b1));
}
__device__ __forceinline__ void cp_async16(uint32_t s, const void* g) {
    asm volatile("cp.async.cg.shared.global [%0], [%1], 16;" :: "r"(s), "l"(g) : "memory");
}
#define CP_COMMIT() asm volatile("cp.async.commit_group;" ::: "memory")
#define CP_WAIT1()  asm volatile("cp.async.wait_group 1;" ::: "memory")
#define CP_WAIT0()  asm volatile("cp.async.wait_group 0;" ::: "memory")

__device__ __forceinline__ uint32_t pack_hi_h(float a, float b) {
    __half2 h = __floats2half2_rn(a, b);
    return *(uint32_t*)&h;
}

// ============================================================================
// convert kernel: fp32 -> fp16
// ============================================================================
__global__ __launch_bounds__(256) void cvt_h_kernel(const float* __restrict__ in,
                                                    __half* __restrict__ o, int n4) {
    int i = blockIdx.x * blockDim.x + threadIdx.x;
    if (i >= n4) return;
    float4 v = ((const float4*)in)[i];
    ((uint2*)o)[i] = make_uint2(pack_hi_h(v.x, v.y), pack_hi_h(v.z, v.w));
}

// ============================================================================
// Shared GEMM config (512 threads, 16 warps 4m x 4n, 32x32 warp tile,
// 3-stage cp.async, 2 CTAs/SM)
// ============================================================================
#define GBK    64
#define GSTR   72
#define GMATB  (128 * GSTR * 2)      // 18432 B
#define GSTAGEB (2 * GMATB)          // 36864 B
#define GEMM_SMEM (3 * GSTAGEB)      // 110592 B

#define GEMM_MAINLOOP(A_, B_ptr, Kdim)                                            \
    const __half* mats[2] = { A_, B_ptr };                                        \
    float acc[2][4][4];                                                           \
    _Pragma("unroll") for (int i = 0; i < 2; i++)                                 \
        _Pragma("unroll") for (int j = 0; j < 4; j++)                             \
            _Pragma("unroll") for (int k = 0; k < 4; k++) acc[i][j][k] = 0.0f;    \
    const int nchunk = (Kdim) / GBK;                                              \
    auto issue = [&](int g) {                                                     \
        const int s = g % 3;                                                      \
        const uint32_t stg = sb + s * GSTAGEB;                                    \
        const int k0 = g * GBK;                                                   \
        _Pragma("unroll") for (int m = 0; m < 2; m++) {                           \
            const __half* src = mats[m] + k0;                                     \
            const uint32_t dstm = stg + m * GMATB;                                \
            _Pragma("unroll") for (int i = 0; i < 2; i++) {                       \
                int id  = t + i * 512;                                            \
                int row = id >> 3, c = id & 7;                                    \
                cp_async16(dstm + (uint32_t)(row * GSTR + c * 8) * 2,             \
                           src + (size_t)row * (Kdim) + c * 8);                   \
            }                                                                     \
        }                                                                         \
        CP_COMMIT();                                                              \
    };                                                                            \
    auto compute = [&](int st) {                                                  \
        const uint32_t base = sb + st * GSTAGEB;                                  \
        const uint32_t aOff = (uint32_t)((wm * 32 + (lane & 15)) * GSTR + (lane >> 4) * 8) * 2; \
        const uint32_t bOff = (uint32_t)((wn * 32 + (lane & 15)) * GSTR + (lane >> 4) * 8) * 2; \
        _Pragma("unroll") for (int kk = 0; kk < 4; kk++) {                        \
            const uint32_t ko = (uint32_t)(kk * 16) * 2;                          \
            uint32_t af[2][4];                                                    \
            _Pragma("unroll") for (int mt = 0; mt < 2; mt++) {                    \
                uint32_t off = aOff + (uint32_t)(mt * 16 * GSTR) * 2 + ko;        \
                ldmatrix_x4(af[mt][0], af[mt][1], af[mt][2], af[mt][3], base + off); \
            }                                                                     \
            uint32_t bf[2][4];                                                    \
            _Pragma("unroll") for (int g = 0; g < 2; g++) {                       \
                uint32_t off = bOff + (uint32_t)(g * 16 * GSTR) * 2 + ko;         \
                ldmatrix_x4(bf[g][0], bf[g][1], bf[g][2], bf[g][3], base + GMATB + off); \
            }                                                                     \
            _Pragma("unroll") for (int mt = 0; mt < 2; mt++) {                    \
                _Pragma("unroll") for (int g = 0; g < 2; g++) {                   \
                    mma_f16(acc[mt][2 * g],     af[mt], bf[g][0], bf[g][2]);      \
                    mma_f16(acc[mt][2 * g + 1], af[mt], bf[g][1], bf[g][3]);      \
                }                                                                 \
            }                                                                     \
        }                                                                         \
    };                                                                            \
    issue(0); issue(1);                                                           \
    for (int c = 0; c < nchunk; c++) {                                            \
        if (c < nchunk - 1) { CP_WAIT1(); } else { CP_WAIT0(); }                  \
        __syncthreads();                                                          \
        if (c + 2 < nchunk) issue(c + 2);                                         \
        compute(c % 3);                                                           \
    }

// ============================================================================
// GEMM2: C[M,N] = A * B^T, fp32 out
// ============================================================================
__global__ __launch_bounds__(512, 2) void gemm_h1(const __half* __restrict__ A,
                                                  const __half* __restrict__ Bw,
                                                  float* __restrict__ C,
                                                  int N, int K, int nBlkN) {
    extern __shared__ char sm[];
    const uint32_t sb = smem_u32(sm);

    int lin = blockIdx.x;
    int grp = lin / (8 * nBlkN);
    int rem = lin - grp * (8 * nBlkN);
    int bm  = grp * 8 + (rem & 7);
    int bn  = rem >> 3;

    const int t = threadIdx.x, lane = t & 31, wid = t >> 5;
    const int wm = wid & 3, wn = wid >> 2;

    GEMM_MAINLOOP(A + (size_t)bm * 128 * K, Bw + (size_t)bn * 128 * K, K)

    const int rowBase = bm * 128 + wm * 32 + (lane >> 2);
    const int colBase = bn * 128 + wn * 32 + (lane & 3) * 2;
#pragma unroll
    for (int mt = 0; mt < 2; mt++) {
#pragma unroll
        for (int nt = 0; nt < 4; nt++) {
            float* c0 = C + (size_t)(rowBase + mt * 16) * N + colBase + nt * 8;
            *(float2*)c0                   = make_float2(acc[mt][nt][0], acc[mt][nt][1]);
            *(float2*)(c0 + (size_t)8 * N) = make_float2(acc[mt][nt][2], acc[mt][nt][3]);
        }
    }
}

// ============================================================================
// GEMM1 + fused RoPE + fp16 epilogue.
// bn<32 -> Q head bn (rope, scale, fp16); 32..39 -> K head (rope, fp16);
// 40..47 -> V head (fp16).
// ============================================================================
#define TSTR 132

__global__ __launch_bounds__(512, 2) void gemm_qkv(const __half* __restrict__ A,
                                                   const __half* __restrict__ Bw,
                                                   const float* __restrict__ cosb,
                                                   const float* __restrict__ sinb,
                                                   __half* __restrict__ qOut,
                                                   __half* __restrict__ kOut,
                                                   __half* __restrict__ vOut) {
    extern __shared__ char sm[];
    const uint32_t sb = smem_u32(sm);
    const int nBlkN = OSZ / 128;

    int lin = blockIdx.x;
    int grp = lin / (8 * nBlkN);
    int rem = lin - grp * (8 * nBlkN);
    int bm  = grp * 8 + (rem & 7);
    int bn  = rem >> 3;

    const int t = threadIdx.x, lane = t & 31, wid = t >> 5;
    const int wm = wid & 3, wn = wid >> 2;

    GEMM_MAINLOOP(A + (size_t)bm * 128 * HID_, Bw + (size_t)bn * 128 * HID_, HID_)

    // ---- epilogue ----
    __syncthreads();
    float* tile = (float*)sm;
    {
        const int r0 = wm * 32 + (lane >> 2);
        const int c0 = wn * 32 + (lane & 3) * 2;
#pragma unroll
        for (int mt = 0; mt < 2; mt++) {
#pragma unroll
            for (int nt = 0; nt < 4; nt++) {
                int r = r0 + mt * 16, c = c0 + nt * 8;
                *(float2*)&tile[r * TSTR + c]       = make_float2(acc[mt][nt][0], acc[mt][nt][1]);
                *(float2*)&tile[(r + 8) * TSTR + c] = make_float2(acc[mt][nt][2], acc[mt][nt][3]);
            }
        }
    }
    __syncthreads();

    const int r  = t >> 2;
    const int qq = t & 3;
    const int tok = bm * 128 + r;
    const float* tr = tile + r * TSTR;

    if (bn < 40) {
        const float4* cp = (const float4*)(cosb + (size_t)tok * HD_);
        const float4* sp = (const float4*)(sinb + (size_t)tok * HD_);
        const bool isQ = bn < 32;
        size_t base = isQ ? ((size_t)tok * QSZ + bn * 128)
                          : ((size_t)tok * KVSZ + (bn - 32) * 128);
        __half* dst = isQ ? qOut : kOut;
        const float sc = isQ ? SCALING : 1.0f;
#pragma unroll
        for (int i = 0; i < 4; i++) {
            int d = qq * 16 + i * 4;
            float4 x1 = *(const float4*)&tr[d];
            float4 x2 = *(const float4*)&tr[d + 64];
            float4 c1 = cp[d >> 2],        s1 = sp[d >> 2];
            float4 c2 = cp[(d + 64) >> 2], s2 = sp[(d + 64) >> 2];
            float4 y1 = make_float4((x1.x * c1.x - x2.x * s1.x) * sc, (x1.y * c1.y - x2.y * s1.y) * sc,
                                    (x1.z * c1.z - x2.z * s1.z) * sc, (x1.w * c1.w - x2.w * s1.w) * sc);
            float4 y2 = make_float4((x2.x * c2.x + x1.x * s2.x) * sc, (x2.y * c2.y + x1.y * s2.y) * sc,
                                    (x2.z * c2.z + x1.z * s2.z) * sc, (x2.w * c2.w + x1.w * s2.w) * sc);
            *(uint2*)(dst + base + d)      = make_uint2(pack_hi_h(y1.x, y1.y), pack_hi_h(y1.z, y1.w));
            *(uint2*)(dst + base + d + 64) = make_uint2(pack_hi_h(y2.x, y2.y), pack_hi_h(y2.z, y2.w));
        }
    } else {
        size_t base = (size_t)tok * KVSZ + (bn - 40) * 128;
#pragma unroll
        for (int i = 0; i < 8; i++) {
            int d = qq * 32 + i * 4;
            float4 x = *(const float4*)&tr[d];
            *(uint2*)(vOut + base + d) = make_uint2(pack_hi_h(x.x, x.y), pack_hi_h(x.z, x.w));
        }
    }
}

// ============================================================================
// Tensor-core flash attention: all-fp16 single-pass QK and PV,
// cp.async K/V double buffer.
// ============================================================================
#define ASTR 136
#define AQB  (128 * ASTR * 2)        // 34816 B
#define AKB  (64 * ASTR * 2)         // 17408 B
#define OFF_Q 0
#define OFF_KV(s) (AQB + (s) * 2 * AKB)      // K at +0, V at +AKB
#define ATTN_SMEM (AQB + 4 * AKB)            // 104448 B

__global__ __launch_bounds__(256, 1) void attn_tc(const __half* __restrict__ qp,
                                                  const __half* __restrict__ kp,
                                                  const __half* __restrict__ vp,
                                                  __half* __restrict__ outh) {
    extern __shared__ char sm[];
    const uint32_t sb = smem_u32(sm);

    const int qt = (int)gridDim.x - 1 - (int)blockIdx.x;
    const int bh = blockIdx.y;
    const int b  = bh >> 5;
    const int h  = bh & 31;
    const int kvh = h >> 2;

    const __half* kbase = kp + (size_t)b * S_ * KVSZ + kvh * HD_;
    const __half* vbase = vp + (size_t)b * S_ * KVSZ + kvh * HD_;

    const int t = threadIdx.x, lane = t & 31, wid = t >> 5;
    const int q0 = qt * 128;
    const int wRow = wid * 16;

    // ---- load Q tile (fp16 copy) ----
#pragma unroll
    for (int i = 0; i < 8; i++) {
        int idx = t + i * 256;
        int r   = idx >> 4;
        int u   = idx & 15;
        size_t src = (size_t)(b * S_ + q0 + r) * QSZ + h * HD_ + u * 8;
        *(uint4*)(sm + OFF_Q + (uint32_t)(r * ASTR + u * 8) * 2) = *(const uint4*)(qp + src);
    }

    const int nkv = qt * 2 + 2;

    auto issue_kv = [&](int kt) {
        const int s = kt & 1;
        const int k0 = kt * 64;
#pragma unroll
        for (int i = 0; i < 4; i++) {
            int idx = t + i * 256;
            int r   = idx >> 4;
            int u   = idx & 15;
            uint32_t off = (uint32_t)(r * ASTR + u * 8) * 2;
            cp_async16(sb + OFF_KV(s) + off,       kbase + (size_t)(k0 + r) * KVSZ + u * 8);
            cp_async16(sb + OFF_KV(s) + AKB + off, vbase + (size_t)(k0 + r) * KVSZ + u * 8);
        }
        CP_COMMIT();
    };

    float m0 = -1e30f, m1 = -1e30f, l0 = 0.0f, l1 = 0.0f;
    float o[16][4];
#pragma unroll
    for (int i = 0; i < 16; i++)
#pragma unroll
        for (int j = 0; j < 4; j++) o[i][j] = 0.0f;

    issue_kv(0);
    for (int kt = 0; kt < nkv; kt++) {
        const int k0 = kt * 64;
        const int st = kt & 1;
        CP_WAIT0();
        __syncthreads();
        if (kt + 1 < nkv) issue_kv(kt + 1);

        // ---- S = Q K^T (single-pass fp16) ----
        float sacc[8][4];
#pragma unroll
        for (int i = 0; i < 8; i++)
#pragma unroll
            for (int j = 0; j < 4; j++) sacc[i][j] = 0.0f;

        const uint32_t aOff = (uint32_t)((wRow + (lane & 15)) * ASTR + (lane >> 4) * 8) * 2;
        const uint32_t bOff = (uint32_t)(((lane & 15)) * ASTR + (lane >> 4) * 8) * 2;
        const uint32_t kvK = sb + OFF_KV(st);
        const uint32_t kvV = kvK + AKB;
#pragma unroll
        for (int kk = 0; kk < 8; kk++) {
            const uint32_t ko = (uint32_t)(kk * 16) * 2;
            uint32_t qf[4];
            ldmatrix_x4(qf[0], qf[1], qf[2], qf[3], sb + OFF_Q + aOff + ko);
#pragma unroll
            for (int g = 0; g < 4; g++) {
                uint32_t off = bOff + (uint32_t)(g * 16 * ASTR) * 2 + ko;
                uint32_t kh[4];
                ldmatrix_x4(kh[0], kh[1], kh[2], kh[3], kvK + off);
                mma_f16(sacc[2 * g],     qf, kh[0], kh[2]);
                mma_f16(sacc[2 * g + 1], qf, kh[1], kh[3]);
            }
        }

        // ---- causal mask ----
        const int r0 = q0 + wRow + (lane >> 2);
        const int r1 = r0 + 8;
        if (k0 + 63 > q0 + wRow) {
#pragma unroll
            for (int nt = 0; nt < 8; nt++) {
                int c = k0 + nt * 8 + (lane & 3) * 2;
                if (c     > r0) sacc[nt][0] = -1e30f;
                if (c + 1 > r0) sacc[nt][1] = -1e30f;
                if (c     > r1) sacc[nt][2] = -1e30f;
                if (c + 1 > r1) sacc[nt][3] = -1e30f;
            }
        }

        // ---- online softmax ----
        float mx0 = m0, mx1 = m1;
#pragma unroll
        for (int nt = 0; nt < 8; nt++) {
            mx0 = fmaxf(mx0, fmaxf(sacc[nt][0], sacc[nt][1]));
            mx1 = fmaxf(mx1, fmaxf(sacc[nt][2], sacc[nt][3]));
        }
        mx0 = fmaxf(mx0, __shfl_xor_sync(0xFFFFFFFFu, mx0, 1));
        mx0 = fmaxf(mx0, __shfl_xor_sync(0xFFFFFFFFu, mx0, 2));
        mx1 = fmaxf(mx1, __shfl_xor_sync(0xFFFFFFFFu, mx1, 1));
        mx1 = fmaxf(mx1, __shfl_xor_sync(0xFFFFFFFFu, mx1, 2));
        float f0 = __expf(m0 - mx0), f1 = __expf(m1 - mx1);
        float sum0 = 0.0f, sum1 = 0.0f;
#pragma unroll
        for (int nt = 0; nt < 8; nt++) {
            sacc[nt][0] = __expf(sacc[nt][0] - mx0);
            sacc[nt][1] = __expf(sacc[nt][1] - mx0);
            sacc[nt][2] = __expf(sacc[nt][2] - mx1);
            sacc[nt][3] = __expf(sacc[nt][3] - mx1);
            sum0 += sacc[nt][0] + sacc[nt][1];
            sum1 += sacc[nt][2] + sacc[nt][3];
        }
        sum0 += __shfl_xor_sync(0xFFFFFFFFu, sum0, 1);
        sum0 += __shfl_xor_sync(0xFFFFFFFFu, sum0, 2);
        sum1 += __shfl_xor_sync(0xFFFFFFFFu, sum1, 1);
        sum1 += __shfl_xor_sync(0xFFFFFFFFu, sum1, 2);
        m0 = mx0; m1 = mx1;
        l0 = l0 * f0 + sum0;
        l1 = l1 * f1 + sum1;
#pragma unroll
        for (int d = 0; d < 16; d++) {
            o[d][0] *= f0; o[d][1] *= f0; o[d][2] *= f1; o[d][3] *= f1;
        }

        // ---- O += P V (single-pass fp16) ----
#pragma unroll
        for (int kt2 = 0; kt2 < 4; kt2++) {
            uint32_t Ph[4];
            Ph[0] = pack_hi_h(sacc[2 * kt2][0],     sacc[2 * kt2][1]);
            Ph[1] = pack_hi_h(sacc[2 * kt2][2],     sacc[2 * kt2][3]);
            Ph[2] = pack_hi_h(sacc[2 * kt2 + 1][0], sacc[2 * kt2 + 1][1]);
            Ph[3] = pack_hi_h(sacc[2 * kt2 + 1][2], sacc[2 * kt2 + 1][3]);

            const int kRow = kt2 * 16 + (lane & 7) + ((lane >> 4) & 1) * 8;
#pragma unroll
            for (int gd = 0; gd < 8; gd++) {
                const int nCol = gd * 16 + ((lane >> 3) & 1) * 8;
                const uint32_t off = (uint32_t)(kRow * ASTR + nCol) * 2;
                uint32_t vh[4];
                ldmatrix_x4t(vh[0], vh[1], vh[2], vh[3], kvV + off);
                mma_f16(o[2 * gd],     Ph, vh[0], vh[2]);
                mma_f16(o[2 * gd + 1], Ph, vh[1], vh[3]);
            }
        }
    }

    // ---- epilogue ----
    const float i0 = 1.0f / l0, i1 = 1.0f / l1;
    const int tok0 = b * S_ + q0 + wRow + (lane >> 2);
    const int tok1 = tok0 + 8;
    const int colB = h * HD_ + (lane & 3) * 2;
#pragma unroll
    for (int d = 0; d < 16; d++) {
        int col = colB + d * 8;
        *(uint32_t*)(outh + (size_t)tok0 * QSZ + col) = pack_hi_h(o[d][0] * i0, o[d][1] * i0);
        *(uint32_t*)(outh + (size_t)tok1 * QSZ + col) = pack_hi_h(o[d][2] * i1, o[d][3] * i1);
    }
}

// ============================================================================
// kernel_launch
// ============================================================================
extern "C" void kernel_launch(void* const* d_in, const int* in_sizes, int n_in,
                              void* d_out, int out_size) {
    const float* hs    = (const float*)d_in[0];
    const float* cosb  = (const float*)d_in[1];
    const float* sinb  = (const float*)d_in[2];
    const float* w_qkv = (const float*)d_in[3];
    const float* w_o   = (const float*)d_in[4];
    float* out = (float*)d_out;

    __half *hsp, *wq, *wo, *qq, *kk, *vv, *at;
    cudaGetSymbolAddress((void**)&hsp, g_hs);
    cudaGetSymbolAddress((void**)&wq,  g_wq);
    cudaGetSymbolAddress((void**)&wo,  g_wo);
    cudaGetSymbolAddress((void**)&qq,  g_q);
    cudaGetSymbolAddress((void**)&kk,  g_k);
    cudaGetSymbolAddress((void**)&vv,  g_v);
    cudaGetSymbolAddress((void**)&at,  g_at);

    cudaFuncSetAttribute(gemm_qkv, cudaFuncAttributeMaxDynamicSharedMemorySize, GEMM_SMEM);
    cudaFuncSetAttribute(gemm_h1,  cudaFuncAttributeMaxDynamicSharedMemorySize, GEMM_SMEM);
    cudaFuncSetAttribute(attn_tc,  cudaFuncAttributeMaxDynamicSharedMemorySize, ATTN_SMEM);

    // 0) operand conversion
    cvt_h_kernel<<<(TOK * HID_ / 4) / 256, 256>>>(hs, hsp, TOK * HID_ / 4);
    cvt_h_kernel<<<(OSZ * HID_ / 4) / 256, 256>>>(w_qkv, wq, OSZ * HID_ / 4);
    cvt_h_kernel<<<(HID_ * QSZ / 4) / 256, 256>>>(w_o, wo, HID_ * QSZ / 4);

    // 1) QKV projection + fused RoPE + fp16
    gemm_qkv<<<(TOK / 128) * (OSZ / 128), 512, GEMM_SMEM>>>(hsp, wq, cosb, sinb,
                                                            qq, kk, vv);

    // 2) Attention
    {
        dim3 grid(S_ / 128, B_ * NH_);
        attn_tc<<<grid, 256, ATTN_SMEM>>>(qq, kk, vv, at);
    }

    // 3) Output projection
    gemm_h1<<<(TOK / 128) * (HID_ / 128), 512, GEMM_SMEM>>>(at, wo, out,
                                                            HID_, QSZ, HID_ / 128);
}

// round 13
// speedup vs baseline: 1.1466x; 1.0027x over previous
#include <cuda_runtime.h>
#include <cuda_bf16.h>
#include <cuda_fp16.h>
#include <cstdint>

// ===== Problem constants =====
#define B_    2
#define S_    2048
#define HID_  4096
#define NH_   32
#define NKV_  8
#define HD_   128
#define QSZ   (NH_ * HD_)
#define KVSZ  (NKV_ * HD_)
#define OSZ   (QSZ + 2 * KVSZ)     // 6144
#define TOK   (B_ * S_)            // 4096
#define SCALING 0.08838834764831843f

// ===== Scratch =====
__device__ __half g_hs[TOK * HID_];
__device__ __half g_wq[OSZ * HID_];
__device__ __half g_wo[HID_ * QSZ];
__device__ __half g_q [TOK * QSZ];
__device__ __half g_k [TOK * KVSZ];
__device__ __half g_v [TOK * KVSZ];
__device__ __half g_at[TOK * QSZ];

// ============================================================================
// PTX helpers
// ============================================================================
__device__ __forceinline__ uint32_t smem_u32(const void* p) {
    uint32_t a;
    asm("{ .reg .u64 t; cvta.to.shared.u64 t, %1; cvt.u32.u64 %0, t; }" : "=r"(a) : "l"(p));
    return a;
}
__device__ __forceinline__ void ldmatrix_x4(uint32_t& r0, uint32_t& r1,
                                            uint32_t& r2, uint32_t& r3, uint32_t addr) {
    asm volatile("ldmatrix.sync.aligned.m8n8.x4.shared.b16 {%0,%1,%2,%3}, [%4];"
                 : "=r"(r0), "=r"(r1), "=r"(r2), "=r"(r3) : "r"(addr));
}
__device__ __forceinline__ void ldmatrix_x4t(uint32_t& r0, uint32_t& r1,
                                             uint32_t& r2, uint32_t& r3, uint32_t addr) {
    asm volatile("ldmatrix.sync.aligned.m8n8.x4.trans.shared.b16 {%0,%1,%2,%3}, [%4];"
                 : "=r"(r0), "=r"(r1), "=r"(r2), "=r"(r3) : "r"(addr));
}
__device__ __forceinline__ void mma_f16(float* d, const uint32_t* a, uint32_t b0, uint32_t b1) {
    asm volatile(
        "mma.sync.aligned.m16n8k16.row.col.f32.f16.f16.f32 "
        "{%0,%1,%2,%3}, {%4,%5,%6,%7}, {%8,%9}, {%0,%1,%2,%3};"
        : "+f"(d[0]), "+f"(d[1]), "+f"(d[2]), "+f"(d[3])
        : "r"(a[0]), "r"(a[1]), "r"(a[2]), "r"(a[3]), "r"(b0), "r"(b1));
}
__device__ __forceinline__ void cp_async16(uint32_t s, const void* g) {
    asm volatile("cp.async.cg.shared.global [%0], [%1], 16;" :: "r"(s), "l"(g) : "memory");
}
#define CP_COMMIT() asm volatile("cp.async.commit_group;" ::: "memory")
#define CP_WAIT1()  asm volatile("cp.async.wait_group 1;" ::: "memory")
#define CP_WAIT0()  asm volatile("cp.async.wait_group 0;" ::: "memory")

__device__ __forceinline__ uint32_t pack_hi_h(float a, float b) {
    __half2 h = __floats2half2_rn(a, b);
    return *(uint32_t*)&h;
}

// ============================================================================
// fused convert kernel: all three fp32 arrays -> fp16 in one launch
// ============================================================================
#define N4_HS (TOK * HID_ / 4)
#define N4_WQ (OSZ * HID_ / 4)
#define N4_WO (HID_ * QSZ / 4)
#define N4_TOTAL (N4_HS + N4_WQ + N4_WO)

__global__ __launch_bounds__(256) void cvt_all_kernel(const float* __restrict__ hs,
                                                      const float* __restrict__ wq,
                                                      const float* __restrict__ wo,
                                                      __half* __restrict__ hsO,
                                                      __half* __restrict__ wqO,
                                                      __half* __restrict__ woO) {
    int i = blockIdx.x * blockDim.x + threadIdx.x;
    const float* in;
    __half* o;
    if (i < N4_HS)                 { in = hs; o = hsO; }
    else if (i < N4_HS + N4_WQ)    { in = wq; o = wqO; i -= N4_HS; }
    else if (i < N4_TOTAL)         { in = wo; o = woO; i -= N4_HS + N4_WQ; }
    else return;
    float4 v = ((const float4*)in)[i];
    ((uint2*)o)[i] = make_uint2(pack_hi_h(v.x, v.y), pack_hi_h(v.z, v.w));
}

// ============================================================================
// Shared GEMM config (512 threads, 16 warps 4m x 4n, 32x32 warp tile,
// 3-stage cp.async, 2 CTAs/SM)
// ============================================================================
#define GBK    64
#define GSTR   72
#define GMATB  (128 * GSTR * 2)
#define GSTAGEB (2 * GMATB)
#define GEMM_SMEM (3 * GSTAGEB)

#define GEMM_MAINLOOP(A_, B_ptr, Kdim)                                            \
    const __half* mats[2] = { A_, B_ptr };                                        \
    float acc[2][4][4];                                                           \
    _Pragma("unroll") for (int i = 0; i < 2; i++)                                 \
        _Pragma("unroll") for (int j = 0; j < 4; j++)                             \
            _Pragma("unroll") for (int k = 0; k < 4; k++) acc[i][j][k] = 0.0f;    \
    const int nchunk = (Kdim) / GBK;                                              \
    auto issue = [&](int g) {                                                     \
        const int s = g % 3;                                                      \
        const uint32_t stg = sb + s * GSTAGEB;                                    \
        const int k0 = g * GBK;                                                   \
        _Pragma("unroll") for (int m = 0; m < 2; m++) {                           \
            const __half* src = mats[m] + k0;                                     \
            const uint32_t dstm = stg + m * GMATB;                                \
            _Pragma("unroll") for (int i = 0; i < 2; i++) {                       \
                int id  = t + i * 512;                                            \
                int row = id >> 3, c = id & 7;                                    \
                cp_async16(dstm + (uint32_t)(row * GSTR + c * 8) * 2,             \
                           src + (size_t)row * (Kdim) + c * 8);                   \
            }                                                                     \
        }                                                                         \
        CP_COMMIT();                                                              \
    };                                                                            \
    auto compute = [&](int st) {                                                  \
        const uint32_t base = sb + st * GSTAGEB;                                  \
        const uint32_t aOff = (uint32_t)((wm * 32 + (lane & 15)) * GSTR + (lane >> 4) * 8) * 2; \
        const uint32_t bOff = (uint32_t)((wn * 32 + (lane & 15)) * GSTR + (lane >> 4) * 8) * 2; \
        _Pragma("unroll") for (int kk = 0; kk < 4; kk++) {                        \
            const uint32_t ko = (uint32_t)(kk * 16) * 2;                          \
            uint32_t af[2][4];                                                    \
            _Pragma("unroll") for (int mt = 0; mt < 2; mt++) {                    \
                uint32_t off = aOff + (uint32_t)(mt * 16 * GSTR) * 2 + ko;        \
                ldmatrix_x4(af[mt][0], af[mt][1], af[mt][2], af[mt][3], base + off); \
            }                                                                     \
            uint32_t bf[2][4];                                                    \
            _Pragma("unroll") for (int g = 0; g < 2; g++) {                       \
                uint32_t off = bOff + (uint32_t)(g * 16 * GSTR) * 2 + ko;         \
                ldmatrix_x4(bf[g][0], bf[g][1], bf[g][2], bf[g][3], base + GMATB + off); \
            }                                                                     \
            _Pragma("unroll") for (int mt = 0; mt < 2; mt++) {                    \
                _Pragma("unroll") for (int g = 0; g < 2; g++) {                   \
                    mma_f16(acc[mt][2 * g],     af[mt], bf[g][0], bf[g][2]);      \
                    mma_f16(acc[mt][2 * g + 1], af[mt], bf[g][1], bf[g][3]);      \
                }                                                                 \
            }                                                                     \
        }                                                                         \
    };                                                                            \
    issue(0); issue(1);                                                           \
    for (int c = 0; c < nchunk; c++) {                                            \
        if (c < nchunk - 1) { CP_WAIT1(); } else { CP_WAIT0(); }                  \
        __syncthreads();                                                          \
        if (c + 2 < nchunk) issue(c + 2);                                         \
        compute(c % 3);                                                           \
    }

// ============================================================================
// GEMM2: C[M,N] = A * B^T, fp32 out
// ============================================================================
__global__ __launch_bounds__(512, 2) void gemm_h1(const __half* __restrict__ A,
                                                  const __half* __restrict__ Bw,
                                                  float* __restrict__ C,
                                                  int N, int K, int nBlkN) {
    extern __shared__ char sm[];
    const uint32_t sb = smem_u32(sm);

    int lin = blockIdx.x;
    int grp = lin / (8 * nBlkN);
    int rem = lin - grp * (8 * nBlkN);
    int bm  = grp * 8 + (rem & 7);
    int bn  = rem >> 3;

    const int t = threadIdx.x, lane = t & 31, wid = t >> 5;
    const int wm = wid & 3, wn = wid >> 2;

    GEMM_MAINLOOP(A + (size_t)bm * 128 * K, Bw + (size_t)bn * 128 * K, K)

    const int rowBase = bm * 128 + wm * 32 + (lane >> 2);
    const int colBase = bn * 128 + wn * 32 + (lane & 3) * 2;
#pragma unroll
    for (int mt = 0; mt < 2; mt++) {
#pragma unroll
        for (int nt = 0; nt < 4; nt++) {
            float* c0 = C + (size_t)(rowBase + mt * 16) * N + colBase + nt * 8;
            *(float2*)c0                   = make_float2(acc[mt][nt][0], acc[mt][nt][1]);
            *(float2*)(c0 + (size_t)8 * N) = make_float2(acc[mt][nt][2], acc[mt][nt][3]);
        }
    }
}

// ============================================================================
// GEMM1 + fused RoPE + fp16 epilogue (unchanged from R12)
// ============================================================================
#define TSTR 132

__global__ __launch_bounds__(512, 2) void gemm_qkv(const __half* __restrict__ A,
                                                   const __half* __restrict__ Bw,
                                                   const float* __restrict__ cosb,
                                                   const float* __restrict__ sinb,
                                                   __half* __restrict__ qOut,
                                                   __half* __restrict__ kOut,
                                                   __half* __restrict__ vOut) {
    extern __shared__ char sm[];
    const uint32_t sb = smem_u32(sm);
    const int nBlkN = OSZ / 128;

    int lin = blockIdx.x;
    int grp = lin / (8 * nBlkN);
    int rem = lin - grp * (8 * nBlkN);
    int bm  = grp * 8 + (rem & 7);
    int bn  = rem >> 3;

    const int t = threadIdx.x, lane = t & 31, wid = t >> 5;
    const int wm = wid & 3, wn = wid >> 2;

    GEMM_MAINLOOP(A + (size_t)bm * 128 * HID_, Bw + (size_t)bn * 128 * HID_, HID_)

    __syncthreads();
    float* tile = (float*)sm;
    {
        const int r0 = wm * 32 + (lane >> 2);
        const int c0 = wn * 32 + (lane & 3) * 2;
#pragma unroll
        for (int mt = 0; mt < 2; mt++) {
#pragma unroll
            for (int nt = 0; nt < 4; nt++) {
                int r = r0 + mt * 16, c = c0 + nt * 8;
                *(float2*)&tile[r * TSTR + c]       = make_float2(acc[mt][nt][0], acc[mt][nt][1]);
                *(float2*)&tile[(r + 8) * TSTR + c] = make_float2(acc[mt][nt][2], acc[mt][nt][3]);
            }
        }
    }
    __syncthreads();

    const int r  = t >> 2;
    const int qq = t & 3;
    const int tok = bm * 128 + r;
    const float* tr = tile + r * TSTR;

    if (bn < 40) {
        const float4* cp = (const float4*)(cosb + (size_t)tok * HD_);
        const float4* sp = (const float4*)(sinb + (size_t)tok * HD_);
        const bool isQ = bn < 32;
        size_t base = isQ ? ((size_t)tok * QSZ + bn * 128)
                          : ((size_t)tok * KVSZ + (bn - 32) * 128);
        __half* dst = isQ ? qOut : kOut;
        const float sc = isQ ? SCALING : 1.0f;
#pragma unroll
        for (int i = 0; i < 4; i++) {
            int d = qq * 16 + i * 4;
            float4 x1 = *(const float4*)&tr[d];
            float4 x2 = *(const float4*)&tr[d + 64];
            float4 c1 = cp[d >> 2],        s1 = sp[d >> 2];
            float4 c2 = cp[(d + 64) >> 2], s2 = sp[(d + 64) >> 2];
            float4 y1 = make_float4((x1.x * c1.x - x2.x * s1.x) * sc, (x1.y * c1.y - x2.y * s1.y) * sc,
                                    (x1.z * c1.z - x2.z * s1.z) * sc, (x1.w * c1.w - x2.w * s1.w) * sc);
            float4 y2 = make_float4((x2.x * c2.x + x1.x * s2.x) * sc, (x2.y * c2.y + x1.y * s2.y) * sc,
                                    (x2.z * c2.z + x1.z * s2.z) * sc, (x2.w * c2.w + x1.w * s2.w) * sc);
            *(uint2*)(dst + base + d)      = make_uint2(pack_hi_h(y1.x, y1.y), pack_hi_h(y1.z, y1.w));
            *(uint2*)(dst + base + d + 64) = make_uint2(pack_hi_h(y2.x, y2.y), pack_hi_h(y2.z, y2.w));
        }
    } else {
        size_t base = (size_t)tok * KVSZ + (bn - 40) * 128;
#pragma unroll
        for (int i = 0; i < 8; i++) {
            int d = qq * 32 + i * 4;
            float4 x = *(const float4*)&tr[d];
            *(uint2*)(vOut + base + d) = make_uint2(pack_hi_h(x.x, x.y), pack_hi_h(x.z, x.w));
        }
    }
}

// ============================================================================
// Tensor-core flash attention: all-fp16, cp.async K/V double buffer.
// NOW 2 CTAs/SM (launch_bounds(256,2)) to fill softmax bubbles.
// ============================================================================
#define ASTR 136
#define AQB  (128 * ASTR * 2)
#define AKB  (64 * ASTR * 2)
#define OFF_Q 0
#define OFF_KV(s) (AQB + (s) * 2 * AKB)
#define ATTN_SMEM (AQB + 4 * AKB)            // 104448 B; x2 = 208896 <= SM limit

__global__ __launch_bounds__(256, 2) void attn_tc(const __half* __restrict__ qp,
                                                  const __half* __restrict__ kp,
                                                  const __half* __restrict__ vp,
                                                  __half* __restrict__ outh) {
    extern __shared__ char sm[];
    const uint32_t sb = smem_u32(sm);

    const int qt = (int)gridDim.x - 1 - (int)blockIdx.x;
    const int bh = blockIdx.y;
    const int b  = bh >> 5;
    const int h  = bh & 31;
    const int kvh = h >> 2;

    const __half* kbase = kp + (size_t)b * S_ * KVSZ + kvh * HD_;
    const __half* vbase = vp + (size_t)b * S_ * KVSZ + kvh * HD_;

    const int t = threadIdx.x, lane = t & 31, wid = t >> 5;
    const int q0 = qt * 128;
    const int wRow = wid * 16;

#pragma unroll
    for (int i = 0; i < 8; i++) {
        int idx = t + i * 256;
        int r   = idx >> 4;
        int u   = idx & 15;
        size_t src = (size_t)(b * S_ + q0 + r) * QSZ + h * HD_ + u * 8;
        *(uint4*)(sm + OFF_Q + (uint32_t)(r * ASTR + u * 8) * 2) = *(const uint4*)(qp + src);
    }

    const int nkv = qt * 2 + 2;

    auto issue_kv = [&](int kt) {
        const int s = kt & 1;
        const int k0 = kt * 64;
#pragma unroll
        for (int i = 0; i < 4; i++) {
            int idx = t + i * 256;
            int r   = idx >> 4;
            int u   = idx & 15;
            uint32_t off = (uint32_t)(r * ASTR + u * 8) * 2;
            cp_async16(sb + OFF_KV(s) + off,       kbase + (size_t)(k0 + r) * KVSZ + u * 8);
            cp_async16(sb + OFF_KV(s) + AKB + off, vbase + (size_t)(k0 + r) * KVSZ + u * 8);
        }
        CP_COMMIT();
    };

    float m0 = -1e30f, m1 = -1e30f, l0 = 0.0f, l1 = 0.0f;
    float o[16][4];
#pragma unroll
    for (int i = 0; i < 16; i++)
#pragma unroll
        for (int j = 0; j < 4; j++) o[i][j] = 0.0f;

    issue_kv(0);
    for (int kt = 0; kt < nkv; kt++) {
        const int k0 = kt * 64;
        const int st = kt & 1;
        CP_WAIT0();
        __syncthreads();
        if (kt + 1 < nkv) issue_kv(kt + 1);

        float sacc[8][4];
#pragma unroll
        for (int i = 0; i < 8; i++)
#pragma unroll
            for (int j = 0; j < 4; j++) sacc[i][j] = 0.0f;

        const uint32_t aOff = (uint32_t)((wRow + (lane & 15)) * ASTR + (lane >> 4) * 8) * 2;
        const uint32_t bOff = (uint32_t)(((lane & 15)) * ASTR + (lane >> 4) * 8) * 2;
        const uint32_t kvK = sb + OFF_KV(st);
        const uint32_t kvV = kvK + AKB;
#pragma unroll
        for (int kk = 0; kk < 8; kk++) {
            const uint32_t ko = (uint32_t)(kk * 16) * 2;
            uint32_t qf[4];
            ldmatrix_x4(qf[0], qf[1], qf[2], qf[3], sb + OFF_Q + aOff + ko);
#pragma unroll
            for (int g = 0; g < 4; g++) {
                uint32_t off = bOff + (uint32_t)(g * 16 * ASTR) * 2 + ko;
                uint32_t kh[4];
                ldmatrix_x4(kh[0], kh[1], kh[2], kh[3], kvK + off);
                mma_f16(sacc[2 * g],     qf, kh[0], kh[2]);
                mma_f16(sacc[2 * g + 1], qf, kh[1], kh[3]);
            }
        }

        const int r0 = q0 + wRow + (lane >> 2);
        const int r1 = r0 + 8;
        if (k0 + 63 > q0 + wRow) {
#pragma unroll
            for (int nt = 0; nt < 8; nt++) {
                int c = k0 + nt * 8 + (lane & 3) * 2;
                if (c     > r0) sacc[nt][0] = -1e30f;
                if (c + 1 > r0) sacc[nt][1] = -1e30f;
                if (c     > r1) sacc[nt][2] = -1e30f;
                if (c + 1 > r1) sacc[nt][3] = -1e30f;
            }
        }

        float mx0 = m0, mx1 = m1;
#pragma unroll
        for (int nt = 0; nt < 8; nt++) {
            mx0 = fmaxf(mx0, fmaxf(sacc[nt][0], sacc[nt][1]));
            mx1 = fmaxf(mx1, fmaxf(sacc[nt][2], sacc[nt][3]));
        }
        mx0 = fmaxf(mx0, __shfl_xor_sync(0xFFFFFFFFu, mx0, 1));
        mx0 = fmaxf(mx0, __shfl_xor_sync(0xFFFFFFFFu, mx0, 2));
        mx1 = fmaxf(mx1, __shfl_xor_sync(0xFFFFFFFFu, mx1, 1));
        mx1 = fmaxf(mx1, __shfl_xor_sync(0xFFFFFFFFu, mx1, 2));
        float f0 = __expf(m0 - mx0), f1 = __expf(m1 - mx1);
        float sum0 = 0.0f, sum1 = 0.0f;
#pragma unroll
        for (int nt = 0; nt < 8; nt++) {
            sacc[nt][0] = __expf(sacc[nt][0] - mx0);
            sacc[nt][1] = __expf(sacc[nt][1] - mx0);
            sacc[nt][2] = __expf(sacc[nt][2] - mx1);
            sacc[nt][3] = __expf(sacc[nt][3] - mx1);
            sum0 += sacc[nt][0] + sacc[nt][1];
            sum1 += sacc[nt][2] + sacc[nt][3];
        }
        sum0 += __shfl_xor_sync(0xFFFFFFFFu, sum0, 1);
        sum0 += __shfl_xor_sync(0xFFFFFFFFu, sum0, 2);
        sum1 += __shfl_xor_sync(0xFFFFFFFFu, sum1, 1);
        sum1 += __shfl_xor_sync(0xFFFFFFFFu, sum1, 2);
        m0 = mx0; m1 = mx1;
        l0 = l0 * f0 + sum0;
        l1 = l1 * f1 + sum1;
#pragma unroll
        for (int d = 0; d < 16; d++) {
            o[d][0] *= f0; o[d][1] *= f0; o[d][2] *= f1; o[d][3] *= f1;
        }

#pragma unroll
        for (int kt2 = 0; kt2 < 4; kt2++) {
            uint32_t Ph[4];
            Ph[0] = pack_hi_h(sacc[2 * kt2][0],     sacc[2 * kt2][1]);
            Ph[1] = pack_hi_h(sacc[2 * kt2][2],     sacc[2 * kt2][3]);
            Ph[2] = pack_hi_h(sacc[2 * kt2 + 1][0], sacc[2 * kt2 + 1][1]);
            Ph[3] = pack_hi_h(sacc[2 * kt2 + 1][2], sacc[2 * kt2 + 1][3]);

            const int kRow = kt2 * 16 + (lane & 7) + ((lane >> 4) & 1) * 8;
#pragma unroll
            for (int gd = 0; gd < 8; gd++) {
                const int nCol = gd * 16 + ((lane >> 3) & 1) * 8;
                const uint32_t off = (uint32_t)(kRow * ASTR + nCol) * 2;
                uint32_t vh[4];
                ldmatrix_x4t(vh[0], vh[1], vh[2], vh[3], kvV + off);
                mma_f16(o[2 * gd],     Ph, vh[0], vh[2]);
                mma_f16(o[2 * gd + 1], Ph, vh[1], vh[3]);
            }
        }
    }

    const float i0 = 1.0f / l0, i1 = 1.0f / l1;
    const int tok0 = b * S_ + q0 + wRow + (lane >> 2);
    const int tok1 = tok0 + 8;
    const int colB = h * HD_ + (lane & 3) * 2;
#pragma unroll
    for (int d = 0; d < 16; d++) {
        int col = colB + d * 8;
        *(uint32_t*)(outh + (size_t)tok0 * QSZ + col) = pack_hi_h(o[d][0] * i0, o[d][1] * i0);
        *(uint32_t*)(outh + (size_t)tok1 * QSZ + col) = pack_hi_h(o[d][2] * i1, o[d][3] * i1);
    }
}

// ============================================================================
// kernel_launch
// ============================================================================
extern "C" void kernel_launch(void* const* d_in, const int* in_sizes, int n_in,
                              void* d_out, int out_size) {
    const float* hs    = (const float*)d_in[0];
    const float* cosb  = (const float*)d_in[1];
    const float* sinb  = (const float*)d_in[2];
    const float* w_qkv = (const float*)d_in[3];
    const float* w_o   = (const float*)d_in[4];
    float* out = (float*)d_out;

    __half *hsp, *wq, *wo, *qq, *kk, *vv, *at;
    cudaGetSymbolAddress((void**)&hsp, g_hs);
    cudaGetSymbolAddress((void**)&wq,  g_wq);
    cudaGetSymbolAddress((void**)&wo,  g_wo);
    cudaGetSymbolAddress((void**)&qq,  g_q);
    cudaGetSymbolAddress((void**)&kk,  g_k);
    cudaGetSymbolAddress((void**)&vv,  g_v);
    cudaGetSymbolAddress((void**)&at,  g_at);

    cudaFuncSetAttribute(gemm_qkv, cudaFuncAttributeMaxDynamicSharedMemorySize, GEMM_SMEM);
    cudaFuncSetAttribute(gemm_h1,  cudaFuncAttributeMaxDynamicSharedMemorySize, GEMM_SMEM);
    cudaFuncSetAttribute(attn_tc,  cudaFuncAttributeMaxDynamicSharedMemorySize, ATTN_SMEM);

    // 0) fused operand conversion (one launch)
    cvt_all_kernel<<<(N4_TOTAL + 255) / 256, 256>>>(hs, w_qkv, w_o, hsp, wq, wo);

    // 1) QKV projection + fused RoPE + fp16
    gemm_qkv<<<(TOK / 128) * (OSZ / 128), 512, GEMM_SMEM>>>(hsp, wq, cosb, sinb,
                                                            qq, kk, vv);

    // 2) Attention (2 CTAs/SM)
    {
        dim3 grid(S_ / 128, B_ * NH_);
        attn_tc<<<grid, 256, ATTN_SMEM>>>(qq, kk, vv, at);
    }

    // 3) Output projection
    gemm_h1<<<(TOK / 128) * (HID_ / 128), 512, GEMM_SMEM>>>(at, wo, out,
                                                            HID_, QSZ, HID_ / 128);
}

// round 14
// speedup vs baseline: 1.1524x; 1.0051x over previous
#include <cuda_runtime.h>
#include <cuda_bf16.h>
#include <cuda_fp16.h>
#include <cstdint>

// ===== Problem constants =====
#define B_    2
#define S_    2048
#define HID_  4096
#define NH_   32
#define NKV_  8
#define HD_   128
#define QSZ   (NH_ * HD_)
#define KVSZ  (NKV_ * HD_)
#define OSZ   (QSZ + 2 * KVSZ)     // 6144
#define TOK   (B_ * S_)            // 4096
#define SCALING 0.08838834764831843f

// ===== Scratch =====
__device__ __half g_hs[TOK * HID_];
__device__ __half g_wq[OSZ * HID_];
__device__ __half g_wo[HID_ * QSZ];
__device__ __half g_q [TOK * QSZ];
__device__ __half g_k [TOK * KVSZ];
__device__ __half g_v [TOK * KVSZ];
__device__ __half g_at[TOK * QSZ];

// ============================================================================
// PTX helpers
// ============================================================================
__device__ __forceinline__ uint32_t smem_u32(const void* p) {
    uint32_t a;
    asm("{ .reg .u64 t; cvta.to.shared.u64 t, %1; cvt.u32.u64 %0, t; }" : "=r"(a) : "l"(p));
    return a;
}
__device__ __forceinline__ void ldmatrix_x4(uint32_t& r0, uint32_t& r1,
                                            uint32_t& r2, uint32_t& r3, uint32_t addr) {
    asm volatile("ldmatrix.sync.aligned.m8n8.x4.shared.b16 {%0,%1,%2,%3}, [%4];"
                 : "=r"(r0), "=r"(r1), "=r"(r2), "=r"(r3) : "r"(addr));
}
__device__ __forceinline__ void ldmatrix_x4t(uint32_t& r0, uint32_t& r1,
                                             uint32_t& r2, uint32_t& r3, uint32_t addr) {
    asm volatile("ldmatrix.sync.aligned.m8n8.x4.trans.shared.b16 {%0,%1,%2,%3}, [%4];"
                 : "=r"(r0), "=r"(r1), "=r"(r2), "=r"(r3) : "r"(addr));
}
__device__ __forceinline__ void mma_f16(float* d, const uint32_t* a, uint32_t b0, uint32_t b1) {
    asm volatile(
        "mma.sync.aligned.m16n8k16.row.col.f32.f16.f16.f32 "
        "{%0,%1,%2,%3}, {%4,%5,%6,%7}, {%8,%9}, {%0,%1,%2,%3};"
        : "+f"(d[0]), "+f"(d[1]), "+f"(d[2]), "+f"(d[3])
        : "r"(a[0]), "r"(a[1]), "r"(a[2]), "r"(a[3]), "r"(b0), "r"(b1));
}
__device__ __forceinline__ void cp_async16(uint32_t s, const void* g) {
    asm volatile("cp.async.cg.shared.global [%0], [%1], 16;" :: "r"(s), "l"(g) : "memory");
}
#define CP_COMMIT() asm volatile("cp.async.commit_group;" ::: "memory")
#define CP_WAIT1()  asm volatile("cp.async.wait_group 1;" ::: "memory")
#define CP_WAIT0()  asm volatile("cp.async.wait_group 0;" ::: "memory")

__device__ __forceinline__ uint32_t pack_hi_h(float a, float b) {
    __half2 h = __floats2half2_rn(a, b);
    return *(uint32_t*)&h;
}

// ============================================================================
// fused convert kernel
// ============================================================================
#define N4_HS (TOK * HID_ / 4)
#define N4_WQ (OSZ * HID_ / 4)
#define N4_WO (HID_ * QSZ / 4)
#define N4_TOTAL (N4_HS + N4_WQ + N4_WO)

__global__ __launch_bounds__(256) void cvt_all_kernel(const float* __restrict__ hs,
                                                      const float* __restrict__ wq,
                                                      const float* __restrict__ wo,
                                                      __half* __restrict__ hsO,
                                                      __half* __restrict__ wqO,
                                                      __half* __restrict__ woO) {
    int i = blockIdx.x * blockDim.x + threadIdx.x;
    const float* in;
    __half* o;
    if (i < N4_HS)                 { in = hs; o = hsO; }
    else if (i < N4_HS + N4_WQ)    { in = wq; o = wqO; i -= N4_HS; }
    else if (i < N4_TOTAL)         { in = wo; o = woO; i -= N4_HS + N4_WQ; }
    else return;
    float4 v = ((const float4*)in)[i];
    ((uint2*)o)[i] = make_uint2(pack_hi_h(v.x, v.y), pack_hi_h(v.z, v.w));
}

// ============================================================================
// GEMM config: 256 threads (8 warps, 4m x 2n, warp tile 32x64), 128x128x64 CTA
// tile, 3-stage cp.async, 2 CTAs/SM. 192 B smem traffic per MMA (was 256).
// ============================================================================
#define GBK    64
#define GSTR   72
#define GMATB  (128 * GSTR * 2)
#define GSTAGEB (2 * GMATB)
#define GEMM_SMEM (3 * GSTAGEB)      // 110592 B

#define GEMM_MAINLOOP(A_, B_ptr, Kdim)                                            \
    const __half* mats[2] = { A_, B_ptr };                                        \
    float acc[2][8][4];                                                           \
    _Pragma("unroll") for (int i = 0; i < 2; i++)                                 \
        _Pragma("unroll") for (int j = 0; j < 8; j++)                             \
            _Pragma("unroll") for (int k = 0; k < 4; k++) acc[i][j][k] = 0.0f;    \
    const int nchunk = (Kdim) / GBK;                                              \
    auto issue = [&](int g) {                                                     \
        const int s = g % 3;                                                      \
        const uint32_t stg = sb + s * GSTAGEB;                                    \
        const int k0 = g * GBK;                                                   \
        _Pragma("unroll") for (int m = 0; m < 2; m++) {                           \
            const __half* src = mats[m] + k0;                                     \
            const uint32_t dstm = stg + m * GMATB;                                \
            _Pragma("unroll") for (int i = 0; i < 4; i++) {                       \
                int id  = t + i * 256;                                            \
                int row = id >> 3, c = id & 7;                                    \
                cp_async16(dstm + (uint32_t)(row * GSTR + c * 8) * 2,             \
                           src + (size_t)row * (Kdim) + c * 8);                   \
            }                                                                     \
        }                                                                         \
        CP_COMMIT();                                                              \
    };                                                                            \
    auto compute = [&](int st) {                                                  \
        const uint32_t base = sb + st * GSTAGEB;                                  \
        const uint32_t aOff = (uint32_t)((wm * 32 + (lane & 15)) * GSTR + (lane >> 4) * 8) * 2; \
        const uint32_t bOff = (uint32_t)((wn * 64 + (lane & 15)) * GSTR + (lane >> 4) * 8) * 2; \
        _Pragma("unroll") for (int kk = 0; kk < 4; kk++) {                        \
            const uint32_t ko = (uint32_t)(kk * 16) * 2;                          \
            uint32_t af[2][4];                                                    \
            _Pragma("unroll") for (int mt = 0; mt < 2; mt++) {                    \
                uint32_t off = aOff + (uint32_t)(mt * 16 * GSTR) * 2 + ko;        \
                ldmatrix_x4(af[mt][0], af[mt][1], af[mt][2], af[mt][3], base + off); \
            }                                                                     \
            uint32_t bf[4][4];                                                    \
            _Pragma("unroll") for (int g = 0; g < 4; g++) {                       \
                uint32_t off = bOff + (uint32_t)(g * 16 * GSTR) * 2 + ko;         \
                ldmatrix_x4(bf[g][0], bf[g][1], bf[g][2], bf[g][3], base + GMATB + off); \
            }                                                                     \
            _Pragma("unroll") for (int mt = 0; mt < 2; mt++) {                    \
                _Pragma("unroll") for (int g = 0; g < 4; g++) {                   \
                    mma_f16(acc[mt][2 * g],     af[mt], bf[g][0], bf[g][2]);      \
                    mma_f16(acc[mt][2 * g + 1], af[mt], bf[g][1], bf[g][3]);      \
                }                                                                 \
            }                                                                     \
        }                                                                         \
    };                                                                            \
    issue(0); issue(1);                                                           \
    for (int c = 0; c < nchunk; c++) {                                            \
        if (c < nchunk - 1) { CP_WAIT1(); } else { CP_WAIT0(); }                  \
        __syncthreads();                                                          \
        if (c + 2 < nchunk) issue(c + 2);                                         \
        compute(c % 3);                                                           \
    }

// ============================================================================
// GEMM2: C[M,N] = A * B^T, fp32 out
// ============================================================================
__global__ __launch_bounds__(256, 2) void gemm_h1(const __half* __restrict__ A,
                                                  const __half* __restrict__ Bw,
                                                  float* __restrict__ C,
                                                  int N, int K, int nBlkN) {
    extern __shared__ char sm[];
    const uint32_t sb = smem_u32(sm);

    int lin = blockIdx.x;
    int grp = lin / (8 * nBlkN);
    int rem = lin - grp * (8 * nBlkN);
    int bm  = grp * 8 + (rem & 7);
    int bn  = rem >> 3;

    const int t = threadIdx.x, lane = t & 31, wid = t >> 5;
    const int wm = wid & 3, wn = wid >> 2;   // 4m x 2n

    GEMM_MAINLOOP(A + (size_t)bm * 128 * K, Bw + (size_t)bn * 128 * K, K)

    const int rowBase = bm * 128 + wm * 32 + (lane >> 2);
    const int colBase = bn * 128 + wn * 64 + (lane & 3) * 2;
#pragma unroll
    for (int mt = 0; mt < 2; mt++) {
#pragma unroll
        for (int nt = 0; nt < 8; nt++) {
            float* c0 = C + (size_t)(rowBase + mt * 16) * N + colBase + nt * 8;
            *(float2*)c0                   = make_float2(acc[mt][nt][0], acc[mt][nt][1]);
            *(float2*)(c0 + (size_t)8 * N) = make_float2(acc[mt][nt][2], acc[mt][nt][3]);
        }
    }
}

// ============================================================================
// GEMM1 + fused RoPE + fp16 epilogue (re-mapped for 256 threads)
// ============================================================================
#define TSTR 132

__global__ __launch_bounds__(256, 2) void gemm_qkv(const __half* __restrict__ A,
                                                   const __half* __restrict__ Bw,
                                                   const float* __restrict__ cosb,
                                                   const float* __restrict__ sinb,
                                                   __half* __restrict__ qOut,
                                                   __half* __restrict__ kOut,
                                                   __half* __restrict__ vOut) {
    extern __shared__ char sm[];
    const uint32_t sb = smem_u32(sm);
    const int nBlkN = OSZ / 128;

    int lin = blockIdx.x;
    int grp = lin / (8 * nBlkN);
    int rem = lin - grp * (8 * nBlkN);
    int bm  = grp * 8 + (rem & 7);
    int bn  = rem >> 3;

    const int t = threadIdx.x, lane = t & 31, wid = t >> 5;
    const int wm = wid & 3, wn = wid >> 2;

    GEMM_MAINLOOP(A + (size_t)bm * 128 * HID_, Bw + (size_t)bn * 128 * HID_, HID_)

    // ---- epilogue: acc -> smem fp32 tile -> rope/split -> fp16 ----
    __syncthreads();
    float* tile = (float*)sm;
    {
        const int r0 = wm * 32 + (lane >> 2);
        const int c0 = wn * 64 + (lane & 3) * 2;
#pragma unroll
        for (int mt = 0; mt < 2; mt++) {
#pragma unroll
            for (int nt = 0; nt < 8; nt++) {
                int r = r0 + mt * 16, c = c0 + nt * 8;
                *(float2*)&tile[r * TSTR + c]       = make_float2(acc[mt][nt][0], acc[mt][nt][1]);
                *(float2*)&tile[(r + 8) * TSTR + c] = make_float2(acc[mt][nt][2], acc[mt][nt][3]);
            }
        }
    }
    __syncthreads();

    // 256 threads: row r = t>>1 (0..127), half hh = t&1
    const int r  = t >> 1;
    const int hh = t & 1;
    const int tok = bm * 128 + r;
    const float* tr = tile + r * TSTR;

    if (bn < 40) {
        const float4* cp = (const float4*)(cosb + (size_t)tok * HD_);
        const float4* sp = (const float4*)(sinb + (size_t)tok * HD_);
        const bool isQ = bn < 32;
        size_t base = isQ ? ((size_t)tok * QSZ + bn * 128)
                          : ((size_t)tok * KVSZ + (bn - 32) * 128);
        __half* dst = isQ ? qOut : kOut;
        const float sc = isQ ? SCALING : 1.0f;
#pragma unroll
        for (int i = 0; i < 8; i++) {
            int d = hh * 32 + i * 4;
            float4 x1 = *(const float4*)&tr[d];
            float4 x2 = *(const float4*)&tr[d + 64];
            float4 c1 = cp[d >> 2],        s1 = sp[d >> 2];
            float4 c2 = cp[(d + 64) >> 2], s2 = sp[(d + 64) >> 2];
            float4 y1 = make_float4((x1.x * c1.x - x2.x * s1.x) * sc, (x1.y * c1.y - x2.y * s1.y) * sc,
                                    (x1.z * c1.z - x2.z * s1.z) * sc, (x1.w * c1.w - x2.w * s1.w) * sc);
            float4 y2 = make_float4((x2.x * c2.x + x1.x * s2.x) * sc, (x2.y * c2.y + x1.y * s2.y) * sc,
                                    (x2.z * c2.z + x1.z * s2.z) * sc, (x2.w * c2.w + x1.w * s2.w) * sc);
            *(uint2*)(dst + base + d)      = make_uint2(pack_hi_h(y1.x, y1.y), pack_hi_h(y1.z, y1.w));
            *(uint2*)(dst + base + d + 64) = make_uint2(pack_hi_h(y2.x, y2.y), pack_hi_h(y2.z, y2.w));
        }
    } else {
        size_t base = (size_t)tok * KVSZ + (bn - 40) * 128;
#pragma unroll
        for (int i = 0; i < 16; i++) {
            int d = hh * 64 + i * 4;
            float4 x = *(const float4*)&tr[d];
            *(uint2*)(vOut + base + d) = make_uint2(pack_hi_h(x.x, x.y), pack_hi_h(x.z, x.w));
        }
    }
}

// ============================================================================
// Tensor-core flash attention (unchanged from R13)
// ============================================================================
#define ASTR 136
#define AQB  (128 * ASTR * 2)
#define AKB  (64 * ASTR * 2)
#define OFF_Q 0
#define OFF_KV(s) (AQB + (s) * 2 * AKB)
#define ATTN_SMEM (AQB + 4 * AKB)

__global__ __launch_bounds__(256, 2) void attn_tc(const __half* __restrict__ qp,
                                                  const __half* __restrict__ kp,
                                                  const __half* __restrict__ vp,
                                                  __half* __restrict__ outh) {
    extern __shared__ char sm[];
    const uint32_t sb = smem_u32(sm);

    const int qt = (int)gridDim.x - 1 - (int)blockIdx.x;
    const int bh = blockIdx.y;
    const int b  = bh >> 5;
    const int h  = bh & 31;
    const int kvh = h >> 2;

    const __half* kbase = kp + (size_t)b * S_ * KVSZ + kvh * HD_;
    const __half* vbase = vp + (size_t)b * S_ * KVSZ + kvh * HD_;

    const int t = threadIdx.x, lane = t & 31, wid = t >> 5;
    const int q0 = qt * 128;
    const int wRow = wid * 16;

#pragma unroll
    for (int i = 0; i < 8; i++) {
        int idx = t + i * 256;
        int r   = idx >> 4;
        int u   = idx & 15;
        size_t src = (size_t)(b * S_ + q0 + r) * QSZ + h * HD_ + u * 8;
        *(uint4*)(sm + OFF_Q + (uint32_t)(r * ASTR + u * 8) * 2) = *(const uint4*)(qp + src);
    }

    const int nkv = qt * 2 + 2;

    auto issue_kv = [&](int kt) {
        const int s = kt & 1;
        const int k0 = kt * 64;
#pragma unroll
        for (int i = 0; i < 4; i++) {
            int idx = t + i * 256;
            int r   = idx >> 4;
            int u   = idx & 15;
            uint32_t off = (uint32_t)(r * ASTR + u * 8) * 2;
            cp_async16(sb + OFF_KV(s) + off,       kbase + (size_t)(k0 + r) * KVSZ + u * 8);
            cp_async16(sb + OFF_KV(s) + AKB + off, vbase + (size_t)(k0 + r) * KVSZ + u * 8);
        }
        CP_COMMIT();
    };

    float m0 = -1e30f, m1 = -1e30f, l0 = 0.0f, l1 = 0.0f;
    float o[16][4];
#pragma unroll
    for (int i = 0; i < 16; i++)
#pragma unroll
        for (int j = 0; j < 4; j++) o[i][j] = 0.0f;

    issue_kv(0);
    for (int kt = 0; kt < nkv; kt++) {
        const int k0 = kt * 64;
        const int st = kt & 1;
        CP_WAIT0();
        __syncthreads();
        if (kt + 1 < nkv) issue_kv(kt + 1);

        float sacc[8][4];
#pragma unroll
        for (int i = 0; i < 8; i++)
#pragma unroll
            for (int j = 0; j < 4; j++) sacc[i][j] = 0.0f;

        const uint32_t aOff = (uint32_t)((wRow + (lane & 15)) * ASTR + (lane >> 4) * 8) * 2;
        const uint32_t bOff = (uint32_t)(((lane & 15)) * ASTR + (lane >> 4) * 8) * 2;
        const uint32_t kvK = sb + OFF_KV(st);
        const uint32_t kvV = kvK + AKB;
#pragma unroll
        for (int kk = 0; kk < 8; kk++) {
            const uint32_t ko = (uint32_t)(kk * 16) * 2;
            uint32_t qf[4];
            ldmatrix_x4(qf[0], qf[1], qf[2], qf[3], sb + OFF_Q + aOff + ko);
#pragma unroll
            for (int g = 0; g < 4; g++) {
                uint32_t off = bOff + (uint32_t)(g * 16 * ASTR) * 2 + ko;
                uint32_t kh[4];
                ldmatrix_x4(kh[0], kh[1], kh[2], kh[3], kvK + off);
                mma_f16(sacc[2 * g],     qf, kh[0], kh[2]);
                mma_f16(sacc[2 * g + 1], qf, kh[1], kh[3]);
            }
        }

        const int r0 = q0 + wRow + (lane >> 2);
        const int r1 = r0 + 8;
        if (k0 + 63 > q0 + wRow) {
#pragma unroll
            for (int nt = 0; nt < 8; nt++) {
                int c = k0 + nt * 8 + (lane & 3) * 2;
                if (c     > r0) sacc[nt][0] = -1e30f;
                if (c + 1 > r0) sacc[nt][1] = -1e30f;
                if (c     > r1) sacc[nt][2] = -1e30f;
                if (c + 1 > r1) sacc[nt][3] = -1e30f;
            }
        }

        float mx0 = m0, mx1 = m1;
#pragma unroll
        for (int nt = 0; nt < 8; nt++) {
            mx0 = fmaxf(mx0, fmaxf(sacc[nt][0], sacc[nt][1]));
            mx1 = fmaxf(mx1, fmaxf(sacc[nt][2], sacc[nt][3]));
        }
        mx0 = fmaxf(mx0, __shfl_xor_sync(0xFFFFFFFFu, mx0, 1));
        mx0 = fmaxf(mx0, __shfl_xor_sync(0xFFFFFFFFu, mx0, 2));
        mx1 = fmaxf(mx1, __shfl_xor_sync(0xFFFFFFFFu, mx1, 1));
        mx1 = fmaxf(mx1, __shfl_xor_sync(0xFFFFFFFFu, mx1, 2));
        float f0 = __expf(m0 - mx0), f1 = __expf(m1 - mx1);
        float sum0 = 0.0f, sum1 = 0.0f;
#pragma unroll
        for (int nt = 0; nt < 8; nt++) {
            sacc[nt][0] = __expf(sacc[nt][0] - mx0);
            sacc[nt][1] = __expf(sacc[nt][1] - mx0);
            sacc[nt][2] = __expf(sacc[nt][2] - mx1);
            sacc[nt][3] = __expf(sacc[nt][3] - mx1);
            sum0 += sacc[nt][0] + sacc[nt][1];
            sum1 += sacc[nt][2] + sacc[nt][3];
        }
        sum0 += __shfl_xor_sync(0xFFFFFFFFu, sum0, 1);
        sum0 += __shfl_xor_sync(0xFFFFFFFFu, sum0, 2);
        sum1 += __shfl_xor_sync(0xFFFFFFFFu, sum1, 1);
        sum1 += __shfl_xor_sync(0xFFFFFFFFu, sum1, 2);
        m0 = mx0; m1 = mx1;
        l0 = l0 * f0 + sum0;
        l1 = l1 * f1 + sum1;
#pragma unroll
        for (int d = 0; d < 16; d++) {
            o[d][0] *= f0; o[d][1] *= f0; o[d][2] *= f1; o[d][3] *= f1;
        }

#pragma unroll
        for (int kt2 = 0; kt2 < 4; kt2++) {
            uint32_t Ph[4];
            Ph[0] = pack_hi_h(sacc[2 * kt2][0],     sacc[2 * kt2][1]);
            Ph[1] = pack_hi_h(sacc[2 * kt2][2],     sacc[2 * kt2][3]);
            Ph[2] = pack_hi_h(sacc[2 * kt2 + 1][0], sacc[2 * kt2 + 1][1]);
            Ph[3] = pack_hi_h(sacc[2 * kt2 + 1][2], sacc[2 * kt2 + 1][3]);

            const int kRow = kt2 * 16 + (lane & 7) + ((lane >> 4) & 1) * 8;
#pragma unroll
            for (int gd = 0; gd < 8; gd++) {
                const int nCol = gd * 16 + ((lane >> 3) & 1) * 8;
                const uint32_t off = (uint32_t)(kRow * ASTR + nCol) * 2;
                uint32_t vh[4];
                ldmatrix_x4t(vh[0], vh[1], vh[2], vh[3], kvV + off);
                mma_f16(o[2 * gd],     Ph, vh[0], vh[2]);
                mma_f16(o[2 * gd + 1], Ph, vh[1], vh[3]);
            }
        }
    }

    const float i0 = 1.0f / l0, i1 = 1.0f / l1;
    const int tok0 = b * S_ + q0 + wRow + (lane >> 2);
    const int tok1 = tok0 + 8;
    const int colB = h * HD_ + (lane & 3) * 2;
#pragma unroll
    for (int d = 0; d < 16; d++) {
        int col = colB + d * 8;
        *(uint32_t*)(outh + (size_t)tok0 * QSZ + col) = pack_hi_h(o[d][0] * i0, o[d][1] * i0);
        *(uint32_t*)(outh + (size_t)tok1 * QSZ + col) = pack_hi_h(o[d][2] * i1, o[d][3] * i1);
    }
}

// ============================================================================
// kernel_launch
// ============================================================================
extern "C" void kernel_launch(void* const* d_in, const int* in_sizes, int n_in,
                              void* d_out, int out_size) {
    const float* hs    = (const float*)d_in[0];
    const float* cosb  = (const float*)d_in[1];
    const float* sinb  = (const float*)d_in[2];
    const float* w_qkv = (const float*)d_in[3];
    const float* w_o   = (const float*)d_in[4];
    float* out = (float*)d_out;

    __half *hsp, *wq, *wo, *qq, *kk, *vv, *at;
    cudaGetSymbolAddress((void**)&hsp, g_hs);
    cudaGetSymbolAddress((void**)&wq,  g_wq);
    cudaGetSymbolAddress((void**)&wo,  g_wo);
    cudaGetSymbolAddress((void**)&qq,  g_q);
    cudaGetSymbolAddress((void**)&kk,  g_k);
    cudaGetSymbolAddress((void**)&vv,  g_v);
    cudaGetSymbolAddress((void**)&at,  g_at);

    cudaFuncSetAttribute(gemm_qkv, cudaFuncAttributeMaxDynamicSharedMemorySize, GEMM_SMEM);
    cudaFuncSetAttribute(gemm_h1,  cudaFuncAttributeMaxDynamicSharedMemorySize, GEMM_SMEM);
    cudaFuncSetAttribute(attn_tc,  cudaFuncAttributeMaxDynamicSharedMemorySize, ATTN_SMEM);

    // 0) fused operand conversion
    cvt_all_kernel<<<(N4_TOTAL + 255) / 256, 256>>>(hs, w_qkv, w_o, hsp, wq, wo);

    // 1) QKV projection + fused RoPE + fp16
    gemm_qkv<<<(TOK / 128) * (OSZ / 128), 256, GEMM_SMEM>>>(hsp, wq, cosb, sinb,
                                                            qq, kk, vv);

    // 2) Attention
    {
        dim3 grid(S_ / 128, B_ * NH_);
        attn_tc<<<grid, 256, ATTN_SMEM>>>(qq, kk, vv, at);
    }

    // 3) Output projection
    gemm_h1<<<(TOK / 128) * (HID_ / 128), 256, GEMM_SMEM>>>(at, wo, out,
                                                            HID_, QSZ, HID_ / 128);
}